// round 1
// baseline (speedup 1.0000x reference)
#include <cuda_runtime.h>
#include <cuda_bf16.h>
#include <math.h>

#define N_NODES 50000
#define E_EDGES 200000
#define A_DIM   2000
#define LRELU_S 0.2f

// ---------------- scratch (static device globals; no allocation) ----------------
__device__ float g_B0[(size_t)N_NODES * 1024];   // fused / gat2 out
__device__ float g_B1[(size_t)N_NODES * 1024];   // xl buffers
__device__ float g_B2[(size_t)N_NODES * 1024];   // gat1 out / gat3 out
__device__ float g_asrc[N_NODES * 4];
__device__ float g_adst[N_NODES * 4];
__device__ float g_alpha[(size_t)E_EDGES * 4];
__device__ float g_alpha_self[N_NODES * 4];
__device__ int   g_deg[N_NODES];
__device__ int   g_off[N_NODES + 1];
__device__ int   g_cur[N_NODES];
__device__ int   g_csrc[E_EDGES];

__device__ __forceinline__ float lrelu(float x) { return x >= 0.f ? x : LRELU_S * x; }

// ---------------- CSR build ----------------
__global__ void k_zero_deg() {
    int i = blockIdx.x * blockDim.x + threadIdx.x;
    if (i < N_NODES) g_deg[i] = 0;
}

__global__ void k_count_deg(const int* __restrict__ dst) {
    int e = blockIdx.x * blockDim.x + threadIdx.x;
    if (e < E_EDGES) atomicAdd(&g_deg[dst[e]], 1);
}

__global__ void k_scan_deg() {
    __shared__ int part[1024];
    int t = threadIdx.x;
    const int chunk = (N_NODES + 1023) / 1024;
    int s = 0;
    for (int i = 0; i < chunk; i++) {
        int idx = t * chunk + i;
        if (idx < N_NODES) s += g_deg[idx];
    }
    part[t] = s;
    __syncthreads();
    int val = s;
    for (int o = 1; o < 1024; o <<= 1) {
        int add = (t >= o) ? part[t - o] : 0;
        __syncthreads();
        val += add;
        part[t] = val;
        __syncthreads();
    }
    int base = val - s;  // exclusive prefix for this thread's chunk
    for (int i = 0; i < chunk; i++) {
        int idx = t * chunk + i;
        if (idx < N_NODES) {
            g_off[idx] = base;
            g_cur[idx] = base;
            base += g_deg[idx];
        }
    }
    if (t == 0) g_off[N_NODES] = E_EDGES;
}

__global__ void k_scatter(const int* __restrict__ src, const int* __restrict__ dst) {
    int e = blockIdx.x * blockDim.x + threadIdx.x;
    if (e < E_EDGES) {
        int p = atomicAdd(&g_cur[dst[e]], 1);
        g_csrc[p] = src[e];
    }
}

// ---------------- struct projection (sparse {0,1} matmul) ----------------
__global__ void k_struct_proj(const float* __restrict__ mh, const float* __restrict__ W,
                              const float* __restrict__ b, float* __restrict__ outB) {
    int warp = (blockIdx.x * blockDim.x + threadIdx.x) >> 5;
    int lane = threadIdx.x & 31;
    if (warp >= N_NODES) return;
    const float* row = mh + (size_t)warp * A_DIM;
    float a0 = 0.f, a1 = 0.f, a2 = 0.f, a3 = 0.f;
    for (int k0 = 0; k0 < A_DIM; k0 += 32) {
        int k = k0 + lane;
        float v = (k < A_DIM) ? row[k] : 0.f;
        unsigned m = __ballot_sync(0xffffffffu, v != 0.f);
        while (m) {
            int j = __ffs(m) - 1;
            m &= m - 1;
            float vj = __shfl_sync(0xffffffffu, v, j);
            const float* wr = W + (size_t)(k0 + j) * 128;
            a0 += wr[lane] * vj;
            a1 += wr[lane + 32] * vj;
            a2 += wr[lane + 64] * vj;
            a3 += wr[lane + 96] * vj;
        }
    }
    float* o = outB + (size_t)warp * 256;
    o[lane]      = a0 + b[lane];
    o[lane + 32] = a1 + b[lane + 32];
    o[lane + 64] = a2 + b[lane + 64];
    o[lane + 96] = a3 + b[lane + 96];
}

// ---------------- SGEMM: C[M,F] = A[M,K] @ B[K,F] (+bias) ----------------
// BM=BN=128, BK=8, 256 threads, 8x8 per thread. F % 128 == 0, K % 8 == 0.
__global__ void k_sgemm(const float* __restrict__ A, int lda,
                        const float* __restrict__ B, int ldb,
                        float* __restrict__ C, int ldc,
                        int M, int K, const float* __restrict__ bias) {
    __shared__ float As[8][128];
    __shared__ float Bs[8][128];
    int tid = threadIdx.x;
    int bm = blockIdx.y * 128;
    int bn = blockIdx.x * 128;
    int tx = tid & 15, ty = tid >> 4;
    int arow = tid >> 1, acol = (tid & 1) * 4;
    int brow = tid >> 5, bcol = (tid & 31) * 4;
    float acc[8][8];
#pragma unroll
    for (int i = 0; i < 8; i++)
#pragma unroll
        for (int j = 0; j < 8; j++) acc[i][j] = 0.f;

    for (int k0 = 0; k0 < K; k0 += 8) {
        float4 av = make_float4(0.f, 0.f, 0.f, 0.f);
        int gr = bm + arow;
        if (gr < M) av = *reinterpret_cast<const float4*>(A + (size_t)gr * lda + k0 + acol);
        As[acol + 0][arow] = av.x;
        As[acol + 1][arow] = av.y;
        As[acol + 2][arow] = av.z;
        As[acol + 3][arow] = av.w;
        float4 bv = *reinterpret_cast<const float4*>(B + (size_t)(k0 + brow) * ldb + bn + bcol);
        *reinterpret_cast<float4*>(&Bs[brow][bcol]) = bv;
        __syncthreads();
#pragma unroll
        for (int kk = 0; kk < 8; kk++) {
            float ra[8], rb[8];
            float4 r0 = *reinterpret_cast<const float4*>(&As[kk][ty * 8]);
            float4 r1 = *reinterpret_cast<const float4*>(&As[kk][ty * 8 + 4]);
            ra[0] = r0.x; ra[1] = r0.y; ra[2] = r0.z; ra[3] = r0.w;
            ra[4] = r1.x; ra[5] = r1.y; ra[6] = r1.z; ra[7] = r1.w;
            float4 c0 = *reinterpret_cast<const float4*>(&Bs[kk][tx * 8]);
            float4 c1 = *reinterpret_cast<const float4*>(&Bs[kk][tx * 8 + 4]);
            rb[0] = c0.x; rb[1] = c0.y; rb[2] = c0.z; rb[3] = c0.w;
            rb[4] = c1.x; rb[5] = c1.y; rb[6] = c1.z; rb[7] = c1.w;
#pragma unroll
            for (int i = 0; i < 8; i++)
#pragma unroll
                for (int j = 0; j < 8; j++) acc[i][j] += ra[i] * rb[j];
        }
        __syncthreads();
    }
#pragma unroll
    for (int i = 0; i < 8; i++) {
        int r = bm + ty * 8 + i;
        if (r >= M) continue;
#pragma unroll
        for (int j = 0; j < 8; j += 4) {
            int c = bn + tx * 8 + j;
            float4 v = make_float4(acc[i][j], acc[i][j + 1], acc[i][j + 2], acc[i][j + 3]);
            if (bias) {
                v.x += bias[c]; v.y += bias[c + 1]; v.z += bias[c + 2]; v.w += bias[c + 3];
            }
            *reinterpret_cast<float4*>(C + (size_t)r * ldc + c) = v;
        }
    }
}

// ---------------- attention scores ----------------
template <int H, int C>
__global__ void k_att_prep(const float* __restrict__ xl, const float* __restrict__ att_src,
                           const float* __restrict__ att_dst) {
    int warp = (blockIdx.x * blockDim.x + threadIdx.x) >> 5;
    int lane = threadIdx.x & 31;
    if (warp >= N_NODES * H) return;
    int n = warp / H, h = warp % H;
    const float* row = xl + (size_t)n * (H * C) + h * C;
    float s = 0.f, d = 0.f;
#pragma unroll 4
    for (int c = lane; c < C; c += 32) {
        float v = row[c];
        s += v * att_src[h * C + c];
        d += v * att_dst[h * C + c];
    }
#pragma unroll
    for (int o = 16; o; o >>= 1) {
        s += __shfl_down_sync(0xffffffffu, s, o);
        d += __shfl_down_sync(0xffffffffu, d, o);
    }
    if (lane == 0) {
        g_asrc[n * H + h] = s;
        g_adst[n * H + h] = d;
    }
}

template <int H>
__global__ void k_attention() {
    int idx = blockIdx.x * blockDim.x + threadIdx.x;
    if (idx >= N_NODES * H) return;
    int n = idx / H, h = idx % H;
    float ad = g_adst[n * H + h];
    int s0 = g_off[n], s1 = g_off[n + 1];
    float eself = lrelu(g_asrc[n * H + h] + ad);
    float mx = eself;
    for (int s = s0; s < s1; s++) {
        float e = lrelu(g_asrc[g_csrc[s] * H + h] + ad);
        mx = fmaxf(mx, e);
    }
    float denom = __expf(eself - mx);
    for (int s = s0; s < s1; s++) {
        float e = lrelu(g_asrc[g_csrc[s] * H + h] + ad);
        denom += __expf(e - mx);
    }
    float inv = 1.f / (denom + 1e-16f);
    g_alpha_self[n * H + h] = __expf(eself - mx) * inv;
    for (int s = s0; s < s1; s++) {
        float e = lrelu(g_asrc[g_csrc[s] * H + h] + ad);
        g_alpha[(size_t)s * H + h] = __expf(e - mx) * inv;
    }
}

// ---------------- aggregation ----------------
// concat=False (head mean): blockDim = C, one block per node
template <int H, int C>
__global__ void k_agg_mean(const float* __restrict__ xl, const float* __restrict__ bias,
                           float* __restrict__ out) {
    int n = blockIdx.x;
    int t = threadIdx.x;
    int s0 = g_off[n], s1 = g_off[n + 1];
    float acc = 0.f;
#pragma unroll
    for (int h = 0; h < H; h++)
        acc += g_alpha_self[n * H + h] * xl[(size_t)n * (H * C) + h * C + t];
    for (int s = s0; s < s1; s++) {
        int src = g_csrc[s];
#pragma unroll
        for (int h = 0; h < H; h++)
            acc += g_alpha[(size_t)s * H + h] * xl[(size_t)src * (H * C) + h * C + t];
    }
    out[(size_t)n * C + t] = acc * (1.f / H) + bias[t];
}

// concat=True, H=4, C=256, F=1024, + optional relu: blockDim = 256
__global__ void k_agg_concat_relu(const float* __restrict__ xl, const float* __restrict__ bias,
                                  float* __restrict__ out) {
    int n = blockIdx.x;
    int t = threadIdx.x;
    int s0 = g_off[n], s1 = g_off[n + 1];
    float acc[4];
#pragma unroll
    for (int j = 0; j < 4; j++)
        acc[j] = g_alpha_self[n * 4 + j] * xl[(size_t)n * 1024 + j * 256 + t];
    for (int s = s0; s < s1; s++) {
        int src = g_csrc[s];
        const float* xr = xl + (size_t)src * 1024;
#pragma unroll
        for (int j = 0; j < 4; j++)
            acc[j] += g_alpha[(size_t)s * 4 + j] * xr[j * 256 + t];
    }
#pragma unroll
    for (int j = 0; j < 4; j++) {
        float v = acc[j] + bias[j * 256 + t];
        out[(size_t)n * 1024 + j * 256 + t] = fmaxf(v, 0.f);
    }
}

// ---------------- double layernorm (C=256), in place ----------------
__global__ void k_double_ln(float* __restrict__ x,
                            const float* __restrict__ g1, const float* __restrict__ b1,
                            const float* __restrict__ g2, const float* __restrict__ b2) {
    __shared__ float sh[256];
    int n = blockIdx.x, t = threadIdx.x;
    float v = x[(size_t)n * 256 + t];

    // LN 1
    sh[t] = v; __syncthreads();
    for (int o = 128; o; o >>= 1) { if (t < o) sh[t] += sh[t + o]; __syncthreads(); }
    float mu = sh[0] * (1.f / 256.f); __syncthreads();
    float d = v - mu;
    sh[t] = d * d; __syncthreads();
    for (int o = 128; o; o >>= 1) { if (t < o) sh[t] += sh[t + o]; __syncthreads(); }
    float var = sh[0] * (1.f / 256.f); __syncthreads();
    v = d * rsqrtf(var + 1e-5f) * g1[t] + b1[t];

    // LN 2
    sh[t] = v; __syncthreads();
    for (int o = 128; o; o >>= 1) { if (t < o) sh[t] += sh[t + o]; __syncthreads(); }
    mu = sh[0] * (1.f / 256.f); __syncthreads();
    d = v - mu;
    sh[t] = d * d; __syncthreads();
    for (int o = 128; o; o >>= 1) { if (t < o) sh[t] += sh[t + o]; __syncthreads(); }
    var = sh[0] * (1.f / 256.f); __syncthreads();
    v = d * rsqrtf(var + 1e-5f) * g2[t] + b2[t];

    x[(size_t)n * 256 + t] = v;
}

// ---------------- mean pool ----------------
__global__ void k_zero_out(float* out) { out[threadIdx.x] = 0.f; }

__global__ void k_pool(const float* __restrict__ x, float* __restrict__ out) {
    int t = threadIdx.x;
    int b = blockIdx.x;
    int rows_per = (N_NODES + gridDim.x - 1) / gridDim.x;
    int r0 = b * rows_per;
    int r1 = min(r0 + rows_per, N_NODES);
    float acc = 0.f;
    for (int r = r0; r < r1; r++) acc += x[(size_t)r * 256 + t];
    atomicAdd(&out[t], acc * (1.f / (float)N_NODES));
}

// ---------------- launch ----------------
extern "C" void kernel_launch(void* const* d_in, const int* in_sizes, int n_in,
                              void* d_out, int out_size) {
    const float* multi_hot = (const float*)d_in[0];
    const float* bert_feat = (const float*)d_in[1];
    const int*   edge      = (const int*)d_in[2];
    const float* W_struct  = (const float*)d_in[3];
    const float* b_struct  = (const float*)d_in[4];
    const float* W_bert    = (const float*)d_in[5];
    const float* b_bert    = (const float*)d_in[6];
    const float* W_g1      = (const float*)d_in[7];
    const float* att_src1  = (const float*)d_in[8];
    const float* att_dst1  = (const float*)d_in[9];
    const float* b_g1      = (const float*)d_in[10];
    const float* W_g2      = (const float*)d_in[11];
    const float* att_src2  = (const float*)d_in[12];
    const float* att_dst2  = (const float*)d_in[13];
    const float* b_g2      = (const float*)d_in[14];
    const float* W_g3      = (const float*)d_in[15];
    const float* att_src3  = (const float*)d_in[16];
    const float* att_dst3  = (const float*)d_in[17];
    const float* b_g3      = (const float*)d_in[18];
    const float* ln1_g     = (const float*)d_in[19];
    const float* ln1_b     = (const float*)d_in[20];
    const float* ln2_g     = (const float*)d_in[21];
    const float* ln2_b     = (const float*)d_in[22];
    float* out = (float*)d_out;

    const int* e_src = edge;
    const int* e_dst = edge + E_EDGES;

    float *B0, *B1, *B2;
    cudaGetSymbolAddress((void**)&B0, g_B0);
    cudaGetSymbolAddress((void**)&B1, g_B1);
    cudaGetSymbolAddress((void**)&B2, g_B2);

    // --- CSR build ---
    k_zero_deg<<<(N_NODES + 255) / 256, 256>>>();
    k_count_deg<<<(E_EDGES + 255) / 256, 256>>>(e_dst);
    k_scan_deg<<<1, 1024>>>();
    k_scatter<<<(E_EDGES + 255) / 256, 256>>>(e_src, e_dst);

    // --- fused features: B0[:, :128] struct, B0[:, 128:] bert ---
    k_struct_proj<<<(N_NODES + 7) / 8, 256>>>(multi_hot, W_struct, b_struct, B0);
    {
        dim3 grid(128 / 128, (N_NODES + 127) / 128);
        k_sgemm<<<grid, 256>>>(bert_feat, 768, W_bert, 128, B0 + 128, 256, N_NODES, 768, b_bert);
    }

    // --- GAT1: 256 -> (2,128) mean -> 128 ---
    {
        dim3 grid(256 / 128, (N_NODES + 127) / 128);
        k_sgemm<<<grid, 256>>>(B0, 256, W_g1, 256, B1, 256, N_NODES, 256, nullptr);
    }
    k_att_prep<2, 128><<<(N_NODES * 2 + 7) / 8, 256>>>(B1, att_src1, att_dst1);
    k_attention<2><<<(N_NODES * 2 + 255) / 256, 256>>>();
    k_agg_mean<2, 128><<<N_NODES, 128>>>(B1, b_g1, B2);

    // --- GAT2: 128 -> (4,256) concat -> 1024, relu ---
    {
        dim3 grid(1024 / 128, (N_NODES + 127) / 128);
        k_sgemm<<<grid, 256>>>(B2, 128, W_g2, 1024, B1, 1024, N_NODES, 128, nullptr);
    }
    k_att_prep<4, 256><<<(N_NODES * 4 + 7) / 8, 256>>>(B1, att_src2, att_dst2);
    k_attention<4><<<(N_NODES * 4 + 255) / 256, 256>>>();
    k_agg_concat_relu<<<N_NODES, 256>>>(B1, b_g2, B0);

    // --- GAT3: 1024 -> (4,256) mean -> 256 ---
    {
        dim3 grid(1024 / 128, (N_NODES + 127) / 128);
        k_sgemm<<<grid, 256>>>(B0, 1024, W_g3, 1024, B1, 1024, N_NODES, 1024, nullptr);
    }
    k_att_prep<4, 256><<<(N_NODES * 4 + 7) / 8, 256>>>(B1, att_src3, att_dst3);
    k_attention<4><<<(N_NODES * 4 + 255) / 256, 256>>>();
    k_agg_mean<4, 256><<<N_NODES, 256>>>(B1, b_g3, B2);

    // --- double LN + mean pool ---
    k_double_ln<<<N_NODES, 256>>>(B2, ln1_g, ln1_b, ln2_g, ln2_b);
    k_zero_out<<<1, 256>>>(out);
    k_pool<<<200, 256>>>(B2, out);
}

// round 5
// speedup vs baseline: 2.0838x; 2.0838x over previous
#include <cuda_runtime.h>
#include <cuda_bf16.h>
#include <math.h>
#include <stdint.h>

#define N_NODES 50000
#define E_EDGES 200000
#define A_DIM   2000
#define LRELU_S 0.2f

// ================= helpers =================
__device__ __forceinline__ uint32_t smem_u32(const void* p) {
    uint32_t a;
    asm("{ .reg .u64 t; cvta.to.shared.u64 t, %1; cvt.u32.u64 %0, t; }" : "=r"(a) : "l"(p));
    return a;
}
#define CP_ASYNC16(dst, src) \
    asm volatile("cp.async.cg.shared.global [%0], [%1], 16;" :: "r"((uint32_t)(dst)), "l"(src) : "memory")
#define CP_COMMIT() asm volatile("cp.async.commit_group;" ::: "memory")
#define CP_WAIT(n)  asm volatile("cp.async.wait_group %0;" :: "n"(n) : "memory")

__device__ __forceinline__ float round_tf32(float x) {
    uint32_t r;
    asm("cvt.rna.tf32.f32 %0, %1;" : "=r"(r) : "f"(x));
    return __uint_as_float(r);
}

__device__ __forceinline__ void mma_tf32(float& c0, float& c1, float& c2, float& c3,
                                         uint32_t a0, uint32_t a1, uint32_t a2, uint32_t a3,
                                         uint32_t b0, uint32_t b1) {
    asm volatile("mma.sync.aligned.m16n8k8.row.col.f32.tf32.tf32.f32 "
                 "{%0,%1,%2,%3}, {%4,%5,%6,%7}, {%8,%9}, {%0,%1,%2,%3};"
                 : "+f"(c0), "+f"(c1), "+f"(c2), "+f"(c3)
                 : "r"(a0), "r"(a1), "r"(a2), "r"(a3), "r"(b0), "r"(b1));
}

// ================= scratch (static globals) =================
__device__ float g_B1[(size_t)N_NODES * 1024];      // xl (GEMM fp32 out)
__device__ float g_B2[(size_t)N_NODES * 256];       // gat3 agg out
__device__ float g_bert_r[(size_t)N_NODES * 768];   // tf32-rounded bert
__device__ float g_fused[(size_t)N_NODES * 256];    // tf32-rounded fused
__device__ float g_x1[(size_t)N_NODES * 128];       // tf32-rounded gat1 agg
__device__ float g_x2[(size_t)N_NODES * 1024];      // tf32-rounded gat2 agg
__device__ float g_Wt[1024 * 1024];                 // tf32-rounded transposed W
__device__ float g_asrc[N_NODES * 4];
__device__ float g_adst[N_NODES * 4];
__device__ float g_alpha[(size_t)E_EDGES * 4];
__device__ float g_alpha_self[N_NODES * 4];
__device__ int   g_deg[N_NODES];
__device__ int   g_off[N_NODES + 1];
__device__ int   g_cur[N_NODES];
__device__ int   g_csrc[E_EDGES];

__device__ __forceinline__ float lrelu(float x) { return x >= 0.f ? x : LRELU_S * x; }

// ================= CSR build =================
__global__ void k_zero_deg() {
    int i = blockIdx.x * blockDim.x + threadIdx.x;
    if (i < N_NODES) g_deg[i] = 0;
}
__global__ void k_count_deg(const int* __restrict__ dst) {
    int e = blockIdx.x * blockDim.x + threadIdx.x;
    if (e < E_EDGES) atomicAdd(&g_deg[dst[e]], 1);
}
__global__ void k_scan_deg() {
    __shared__ int part[1024];
    int t = threadIdx.x;
    const int chunk = (N_NODES + 1023) / 1024;
    int s = 0;
    for (int i = 0; i < chunk; i++) {
        int idx = t * chunk + i;
        if (idx < N_NODES) s += g_deg[idx];
    }
    part[t] = s;
    __syncthreads();
    int val = s;
    for (int o = 1; o < 1024; o <<= 1) {
        int add = (t >= o) ? part[t - o] : 0;
        __syncthreads();
        val += add;
        part[t] = val;
        __syncthreads();
    }
    int base = val - s;
    for (int i = 0; i < chunk; i++) {
        int idx = t * chunk + i;
        if (idx < N_NODES) {
            g_off[idx] = base;
            g_cur[idx] = base;
            base += g_deg[idx];
        }
    }
    if (t == 0) g_off[N_NODES] = E_EDGES;
}
__global__ void k_scatter(const int* __restrict__ src, const int* __restrict__ dst) {
    int e = blockIdx.x * blockDim.x + threadIdx.x;
    if (e < E_EDGES) {
        int p = atomicAdd(&g_cur[dst[e]], 1);
        g_csrc[p] = src[e];
    }
}

// ================= converts =================
__global__ void k_round_tf32(const float* __restrict__ in, float* __restrict__ out, size_t n4) {
    size_t i = (size_t)blockIdx.x * blockDim.x + threadIdx.x;
    if (i < n4) {
        float4 v = reinterpret_cast<const float4*>(in)[i];
        v.x = round_tf32(v.x); v.y = round_tf32(v.y);
        v.z = round_tf32(v.z); v.w = round_tf32(v.w);
        reinterpret_cast<float4*>(out)[i] = v;
    }
}
// Wt[n*K + k] = round_tf32(W[k*N + n])
__global__ void k_transp(const float* __restrict__ W, float* __restrict__ Wt, int K, int N) {
    int i = blockIdx.x * blockDim.x + threadIdx.x;
    if (i < K * N) {
        int k = i / N, n = i % N;
        Wt[(size_t)n * K + k] = round_tf32(W[i]);
    }
}

// ================= struct projection (sparse {0,1} matmul) -> tf32 =================
__global__ void k_struct_proj(const float* __restrict__ mh, const float* __restrict__ W,
                              const float* __restrict__ b, float* __restrict__ outB) {
    int warp = (blockIdx.x * blockDim.x + threadIdx.x) >> 5;
    int lane = threadIdx.x & 31;
    if (warp >= N_NODES) return;
    const float* row = mh + (size_t)warp * A_DIM;
    float a0 = 0.f, a1 = 0.f, a2 = 0.f, a3 = 0.f;
    for (int k0 = 0; k0 < A_DIM; k0 += 32) {
        int k = k0 + lane;
        float v = (k < A_DIM) ? row[k] : 0.f;
        unsigned m = __ballot_sync(0xffffffffu, v != 0.f);
        while (m) {
            int j = __ffs(m) - 1;
            m &= m - 1;
            float vj = __shfl_sync(0xffffffffu, v, j);
            const float* wr = W + (size_t)(k0 + j) * 128;
            a0 += wr[lane] * vj;
            a1 += wr[lane + 32] * vj;
            a2 += wr[lane + 64] * vj;
            a3 += wr[lane + 96] * vj;
        }
    }
    float* o = outB + (size_t)warp * 256;
    o[lane]      = round_tf32(a0 + b[lane]);
    o[lane + 32] = round_tf32(a1 + b[lane + 32]);
    o[lane + 64] = round_tf32(a2 + b[lane + 64]);
    o[lane + 96] = round_tf32(a3 + b[lane + 96]);
}

// ================= tf32 HMMA GEMM =================
// C[M, N] = A[M, K] @ Wt[N, K]^T   (tf32 in, fp32 acc)
// BM=128, BN=128, BK=32, 256 threads, 8 warps (2 m x 4 n), warp tile 64x32.
// grid: (N/128, ceil(M/128)). smem row stride 144B (36 words, conflict-free).
template <bool OUT_TF32>
__global__ void __launch_bounds__(256, 1)
k_hgemm(const float* __restrict__ A, const float* __restrict__ Bt,
        float* __restrict__ C, int M, int K, int ldc, const float* __restrict__ bias) {
    constexpr int S = 3;
    constexpr int ROW_B = 144;                   // bytes per 32-float row
    constexpr int TILE_BYTES = 128 * ROW_B;      // 18432
    constexpr int STAGE = 2 * TILE_BYTES;

    extern __shared__ char smem[];
    uint32_t sb = smem_u32(smem);

    int tid = threadIdx.x;
    int wid = tid >> 5;
    int lane = tid & 31;
    int wm = wid & 1;        // 0..1
    int wn = wid >> 1;       // 0..3
    int bm = blockIdx.y * 128;
    int bn = blockIdx.x * 128;
    int KI = K / 32;

    int qrow = lane >> 2;        // 0..7
    int qk   = lane & 3;         // 0..3
    int qcol = qk * 2;           // epilogue col pairs

    float acc[4][4][4];
#pragma unroll
    for (int i = 0; i < 4; i++)
#pragma unroll
        for (int j = 0; j < 4; j++)
#pragma unroll
            for (int r = 0; r < 4; r++) acc[i][j][r] = 0.f;

    auto load_stage = [&](int kt, int s) {
        int k0 = kt * 32;
#pragma unroll
        for (int j = 0; j < 4; j++) {                 // A: 1024 chunks / 256 thr
            int ci = tid + j * 256;
            int row = ci >> 3, cp = ci & 7;
            uint32_t dst = sb + s * STAGE + row * ROW_B + cp * 16;
            if (bm + row < M)
                CP_ASYNC16(dst, A + (size_t)(bm + row) * K + k0 + cp * 4);
        }
#pragma unroll
        for (int j = 0; j < 4; j++) {                 // B
            int ci = tid + j * 256;
            int row = ci >> 3, cp = ci & 7;
            uint32_t dst = sb + s * STAGE + TILE_BYTES + row * ROW_B + cp * 16;
            CP_ASYNC16(dst, Bt + (size_t)(bn + row) * K + k0 + cp * 4);
        }
    };

    load_stage(0, 0); CP_COMMIT();
    if (KI > 1) load_stage(1, 1);
    CP_COMMIT();

    for (int kt = 0; kt < KI; kt++) {
        int s = kt % S;
        CP_WAIT(1);
        __syncthreads();
        const char* As = smem + s * STAGE;
        const char* Bs = smem + s * STAGE + TILE_BYTES;
#pragma unroll
        for (int kk = 0; kk < 32; kk += 8) {
            uint32_t af[4][4], bf[4][2];
#pragma unroll
            for (int mt = 0; mt < 4; mt++) {
                int r0 = wm * 64 + mt * 16 + qrow;
                const char* p = As + r0 * ROW_B + (kk + qk) * 4;
                af[mt][0] = *reinterpret_cast<const uint32_t*>(p);
                af[mt][1] = *reinterpret_cast<const uint32_t*>(p + 8 * ROW_B);
                af[mt][2] = *reinterpret_cast<const uint32_t*>(p + 16);
                af[mt][3] = *reinterpret_cast<const uint32_t*>(p + 8 * ROW_B + 16);
            }
#pragma unroll
            for (int nt = 0; nt < 4; nt++) {
                int n0 = wn * 32 + nt * 8 + qrow;
                const char* p = Bs + n0 * ROW_B + (kk + qk) * 4;
                bf[nt][0] = *reinterpret_cast<const uint32_t*>(p);
                bf[nt][1] = *reinterpret_cast<const uint32_t*>(p + 16);
            }
#pragma unroll
            for (int mt = 0; mt < 4; mt++)
#pragma unroll
                for (int nt = 0; nt < 4; nt++)
                    mma_tf32(acc[mt][nt][0], acc[mt][nt][1], acc[mt][nt][2], acc[mt][nt][3],
                             af[mt][0], af[mt][1], af[mt][2], af[mt][3],
                             bf[nt][0], bf[nt][1]);
        }
        int kn = kt + 2;
        if (kn < KI) load_stage(kn, kn % S);
        CP_COMMIT();
    }

    // ---- epilogue ----
#pragma unroll
    for (int mt = 0; mt < 4; mt++) {
        int r0 = bm + wm * 64 + mt * 16 + qrow;
#pragma unroll
        for (int nt = 0; nt < 4; nt++) {
            int c = bn + wn * 32 + nt * 8 + qcol;
            float v0 = acc[mt][nt][0], v1 = acc[mt][nt][1];
            float v2 = acc[mt][nt][2], v3 = acc[mt][nt][3];
            if (bias) {
                float b0 = bias[c], b1 = bias[c + 1];
                v0 += b0; v1 += b1; v2 += b0; v3 += b1;
            }
            if (OUT_TF32) {
                v0 = round_tf32(v0); v1 = round_tf32(v1);
                v2 = round_tf32(v2); v3 = round_tf32(v3);
            }
            if (r0 < M)
                *reinterpret_cast<float2*>(C + (size_t)r0 * ldc + c) = make_float2(v0, v1);
            if (r0 + 8 < M)
                *reinterpret_cast<float2*>(C + (size_t)(r0 + 8) * ldc + c) = make_float2(v2, v3);
        }
    }
}

// ================= attention scores =================
template <int H, int C>
__global__ void k_att_prep(const float* __restrict__ xl, const float* __restrict__ att_src,
                           const float* __restrict__ att_dst) {
    int warp = (blockIdx.x * blockDim.x + threadIdx.x) >> 5;
    int lane = threadIdx.x & 31;
    if (warp >= N_NODES * H) return;
    int n = warp / H, h = warp % H;
    const float* row = xl + (size_t)n * (H * C) + h * C;
    float s = 0.f, d = 0.f;
#pragma unroll 4
    for (int c = lane; c < C; c += 32) {
        float v = row[c];
        s += v * att_src[h * C + c];
        d += v * att_dst[h * C + c];
    }
#pragma unroll
    for (int o = 16; o; o >>= 1) {
        s += __shfl_down_sync(0xffffffffu, s, o);
        d += __shfl_down_sync(0xffffffffu, d, o);
    }
    if (lane == 0) {
        g_asrc[n * H + h] = s;
        g_adst[n * H + h] = d;
    }
}

template <int H>
__global__ void k_attention() {
    int idx = blockIdx.x * blockDim.x + threadIdx.x;
    if (idx >= N_NODES * H) return;
    int n = idx / H, h = idx % H;
    float ad = g_adst[n * H + h];
    int s0 = g_off[n], s1 = g_off[n + 1];
    float eself = lrelu(g_asrc[n * H + h] + ad);
    float mx = eself;
    for (int s = s0; s < s1; s++) {
        float e = lrelu(g_asrc[g_csrc[s] * H + h] + ad);
        mx = fmaxf(mx, e);
    }
    float denom = __expf(eself - mx);
    for (int s = s0; s < s1; s++) {
        float e = lrelu(g_asrc[g_csrc[s] * H + h] + ad);
        denom += __expf(e - mx);
    }
    float inv = 1.f / (denom + 1e-16f);
    g_alpha_self[n * H + h] = __expf(eself - mx) * inv;
    for (int s = s0; s < s1; s++) {
        float e = lrelu(g_asrc[g_csrc[s] * H + h] + ad);
        g_alpha[(size_t)s * H + h] = __expf(e - mx) * inv;
    }
}

// ================= aggregation =================
// ROUND: round output to tf32 (feeds next GEMM)
template <int H, int C, bool ROUND>
__global__ void k_agg_mean(const float* __restrict__ xl, const float* __restrict__ bias,
                           float* __restrict__ out) {
    int n = blockIdx.x;
    int t = threadIdx.x;
    int s0 = g_off[n], s1 = g_off[n + 1];
    float acc = 0.f;
#pragma unroll
    for (int h = 0; h < H; h++)
        acc += g_alpha_self[n * H + h] * xl[(size_t)n * (H * C) + h * C + t];
    for (int s = s0; s < s1; s++) {
        int src = g_csrc[s];
#pragma unroll
        for (int h = 0; h < H; h++)
            acc += g_alpha[(size_t)s * H + h] * xl[(size_t)src * (H * C) + h * C + t];
    }
    float v = acc * (1.f / H) + bias[t];
    out[(size_t)n * C + t] = ROUND ? round_tf32(v) : v;
}

__global__ void k_agg_concat_relu(const float* __restrict__ xl, const float* __restrict__ bias,
                                  float* __restrict__ out) {
    int n = blockIdx.x;
    int t = threadIdx.x;
    int s0 = g_off[n], s1 = g_off[n + 1];
    float acc[4];
#pragma unroll
    for (int j = 0; j < 4; j++)
        acc[j] = g_alpha_self[n * 4 + j] * xl[(size_t)n * 1024 + j * 256 + t];
    for (int s = s0; s < s1; s++) {
        int src = g_csrc[s];
        const float* xr = xl + (size_t)src * 1024;
#pragma unroll
        for (int j = 0; j < 4; j++)
            acc[j] += g_alpha[(size_t)s * 4 + j] * xr[j * 256 + t];
    }
#pragma unroll
    for (int j = 0; j < 4; j++) {
        float v = acc[j] + bias[j * 256 + t];
        out[(size_t)n * 1024 + j * 256 + t] = round_tf32(fmaxf(v, 0.f));
    }
}

// ================= double layernorm (C=256) =================
__global__ void k_double_ln(float* __restrict__ x,
                            const float* __restrict__ g1, const float* __restrict__ b1,
                            const float* __restrict__ g2, const float* __restrict__ b2) {
    __shared__ float sh[256];
    int n = blockIdx.x, t = threadIdx.x;
    float v = x[(size_t)n * 256 + t];

    sh[t] = v; __syncthreads();
    for (int o = 128; o; o >>= 1) { if (t < o) sh[t] += sh[t + o]; __syncthreads(); }
    float mu = sh[0] * (1.f / 256.f); __syncthreads();
    float d = v - mu;
    sh[t] = d * d; __syncthreads();
    for (int o = 128; o; o >>= 1) { if (t < o) sh[t] += sh[t + o]; __syncthreads(); }
    float var = sh[0] * (1.f / 256.f); __syncthreads();
    v = d * rsqrtf(var + 1e-5f) * g1[t] + b1[t];

    sh[t] = v; __syncthreads();
    for (int o = 128; o; o >>= 1) { if (t < o) sh[t] += sh[t + o]; __syncthreads(); }
    mu = sh[0] * (1.f / 256.f); __syncthreads();
    d = v - mu;
    sh[t] = d * d; __syncthreads();
    for (int o = 128; o; o >>= 1) { if (t < o) sh[t] += sh[t + o]; __syncthreads(); }
    var = sh[0] * (1.f / 256.f); __syncthreads();
    v = d * rsqrtf(var + 1e-5f) * g2[t] + b2[t];

    x[(size_t)n * 256 + t] = v;
}

// ================= mean pool =================
__global__ void k_zero_out(float* out) { out[threadIdx.x] = 0.f; }
__global__ void k_pool(const float* __restrict__ x, float* __restrict__ out) {
    int t = threadIdx.x;
    int b = blockIdx.x;
    int rows_per = (N_NODES + gridDim.x - 1) / gridDim.x;
    int r0 = b * rows_per;
    int r1 = min(r0 + rows_per, N_NODES);
    float acc = 0.f;
    for (int r = r0; r < r1; r++) acc += x[(size_t)r * 256 + t];
    atomicAdd(&out[t], acc * (1.f / (float)N_NODES));
}

// ================= launch =================
extern "C" void kernel_launch(void* const* d_in, const int* in_sizes, int n_in,
                              void* d_out, int out_size) {
    const float* multi_hot = (const float*)d_in[0];
    const float* bert_feat = (const float*)d_in[1];
    const int*   edge      = (const int*)d_in[2];
    const float* W_struct  = (const float*)d_in[3];
    const float* b_struct  = (const float*)d_in[4];
    const float* W_bert    = (const float*)d_in[5];
    const float* b_bert    = (const float*)d_in[6];
    const float* W_g1      = (const float*)d_in[7];
    const float* att_src1  = (const float*)d_in[8];
    const float* att_dst1  = (const float*)d_in[9];
    const float* b_g1      = (const float*)d_in[10];
    const float* W_g2      = (const float*)d_in[11];
    const float* att_src2  = (const float*)d_in[12];
    const float* att_dst2  = (const float*)d_in[13];
    const float* b_g2      = (const float*)d_in[14];
    const float* W_g3      = (const float*)d_in[15];
    const float* att_src3  = (const float*)d_in[16];
    const float* att_dst3  = (const float*)d_in[17];
    const float* b_g3      = (const float*)d_in[18];
    const float* ln1_g     = (const float*)d_in[19];
    const float* ln1_b     = (const float*)d_in[20];
    const float* ln2_g     = (const float*)d_in[21];
    const float* ln2_b     = (const float*)d_in[22];
    float* out = (float*)d_out;

    const int* e_src = edge;
    const int* e_dst = edge + E_EDGES;

    float *B1, *B2, *bertR, *fused, *x1, *x2, *Wt;
    cudaGetSymbolAddress((void**)&B1, g_B1);
    cudaGetSymbolAddress((void**)&B2, g_B2);
    cudaGetSymbolAddress((void**)&bertR, g_bert_r);
    cudaGetSymbolAddress((void**)&fused, g_fused);
    cudaGetSymbolAddress((void**)&x1, g_x1);
    cudaGetSymbolAddress((void**)&x2, g_x2);
    cudaGetSymbolAddress((void**)&Wt, g_Wt);

    const int SMEM = 3 * 2 * 128 * 144;   // 110592
    cudaFuncSetAttribute(k_hgemm<true>,  cudaFuncAttributeMaxDynamicSharedMemorySize, SMEM);
    cudaFuncSetAttribute(k_hgemm<false>, cudaFuncAttributeMaxDynamicSharedMemorySize, SMEM);

    const int MB = (N_NODES + 127) / 128;   // 391

    // --- CSR build ---
    k_zero_deg<<<(N_NODES + 255) / 256, 256>>>();
    k_count_deg<<<(E_EDGES + 255) / 256, 256>>>(e_dst);
    k_scan_deg<<<1, 1024>>>();
    k_scatter<<<(E_EDGES + 255) / 256, 256>>>(e_src, e_dst);

    // --- round bert + fused features (tf32) ---
    {
        size_t n4 = (size_t)N_NODES * 768 / 4;
        k_round_tf32<<<(unsigned)((n4 + 255) / 256), 256>>>(bert_feat, bertR, n4);
    }
    k_struct_proj<<<(N_NODES + 7) / 8, 256>>>(multi_hot, W_struct, b_struct, fused);
    k_transp<<<(768 * 128 + 255) / 256, 256>>>(W_bert, Wt, 768, 128);
    k_hgemm<true><<<dim3(1, MB), 256, SMEM>>>(bertR, Wt, fused + 128, N_NODES, 768, 256, b_bert);

    // --- GAT1: 256 -> (2,128) mean -> 128 ---
    k_transp<<<(256 * 256 + 255) / 256, 256>>>(W_g1, Wt, 256, 256);
    k_hgemm<false><<<dim3(2, MB), 256, SMEM>>>(fused, Wt, B1, N_NODES, 256, 256, nullptr);
    k_att_prep<2, 128><<<(N_NODES * 2 + 7) / 8, 256>>>(B1, att_src1, att_dst1);
    k_attention<2><<<(N_NODES * 2 + 255) / 256, 256>>>();
    k_agg_mean<2, 128, true><<<N_NODES, 128>>>(B1, b_g1, x1);

    // --- GAT2: 128 -> (4,256) concat -> 1024, relu ---
    k_transp<<<(128 * 1024 + 255) / 256, 256>>>(W_g2, Wt, 128, 1024);
    k_hgemm<false><<<dim3(8, MB), 256, SMEM>>>(x1, Wt, B1, N_NODES, 128, 1024, nullptr);
    k_att_prep<4, 256><<<(N_NODES * 4 + 7) / 8, 256>>>(B1, att_src2, att_dst2);
    k_attention<4><<<(N_NODES * 4 + 255) / 256, 256>>>();
    k_agg_concat_relu<<<N_NODES, 256>>>(B1, b_g2, x2);

    // --- GAT3: 1024 -> (4,256) mean -> 256 ---
    k_transp<<<(1024 * 1024 + 255) / 256, 256>>>(W_g3, Wt, 1024, 1024);
    k_hgemm<false><<<dim3(8, MB), 256, SMEM>>>(x2, Wt, B1, N_NODES, 1024, 1024, nullptr);
    k_att_prep<4, 256><<<(N_NODES * 4 + 7) / 8, 256>>>(B1, att_src3, att_dst3);
    k_attention<4><<<(N_NODES * 4 + 255) / 256, 256>>>();
    k_agg_mean<4, 256, false><<<N_NODES, 256>>>(B1, b_g3, B2);

    // --- double LN + mean pool ---
    k_double_ln<<<N_NODES, 256>>>(B2, ln1_g, ln1_b, ln2_g, ln2_b);
    k_zero_out<<<1, 256>>>(out);
    k_pool<<<200, 256>>>(B2, out);
}

// round 6
// speedup vs baseline: 2.4781x; 1.1892x over previous
#include <cuda_runtime.h>
#include <cuda_bf16.h>
#include <math.h>
#include <stdint.h>

#define N_NODES 50000
#define E_EDGES 200000
#define A_DIM   2000
#define LRELU_S 0.2f

// ================= helpers =================
__device__ __forceinline__ uint32_t smem_u32(const void* p) {
    uint32_t a;
    asm("{ .reg .u64 t; cvta.to.shared.u64 t, %1; cvt.u32.u64 %0, t; }" : "=r"(a) : "l"(p));
    return a;
}
#define CP_ASYNC16(dst, src) \
    asm volatile("cp.async.cg.shared.global [%0], [%1], 16;" :: "r"((uint32_t)(dst)), "l"(src) : "memory")
#define CP_COMMIT() asm volatile("cp.async.commit_group;" ::: "memory")
#define CP_WAIT(n)  asm volatile("cp.async.wait_group %0;" :: "n"(n) : "memory")

__device__ __forceinline__ float round_tf32(float x) {
    uint32_t r;
    asm("cvt.rna.tf32.f32 %0, %1;" : "=r"(r) : "f"(x));
    return __uint_as_float(r);
}
__device__ __forceinline__ uint32_t round_tf32_u(uint32_t x) {
    uint32_t r;
    asm("cvt.rna.tf32.f32 %0, %1;" : "=r"(r) : "f"(__uint_as_float(x)));
    return r;
}

__device__ __forceinline__ void mma_tf32(float& c0, float& c1, float& c2, float& c3,
                                         uint32_t a0, uint32_t a1, uint32_t a2, uint32_t a3,
                                         uint32_t b0, uint32_t b1) {
    asm volatile("mma.sync.aligned.m16n8k8.row.col.f32.tf32.tf32.f32 "
                 "{%0,%1,%2,%3}, {%4,%5,%6,%7}, {%8,%9}, {%0,%1,%2,%3};"
                 : "+f"(c0), "+f"(c1), "+f"(c2), "+f"(c3)
                 : "r"(a0), "r"(a1), "r"(a2), "r"(a3), "r"(b0), "r"(b1));
}

// ================= scratch (static globals) =================
__device__ __nv_bfloat16 g_xl[(size_t)N_NODES * 1024];   // xl (GEMM bf16 out)
__device__ float g_B2[(size_t)N_NODES * 256];            // gat3 agg out
__device__ float g_fused[(size_t)N_NODES * 256];         // tf32-rounded fused
__device__ float g_x1[(size_t)N_NODES * 128];            // tf32-rounded gat1 agg
__device__ float g_x2[(size_t)N_NODES * 1024];           // tf32-rounded gat2 agg
__device__ float g_Wt[1024 * 1024];                      // tf32-rounded transposed W
__device__ float g_asrc[N_NODES * 4];
__device__ float g_adst[N_NODES * 4];
__device__ float g_alpha[(size_t)E_EDGES * 4];
__device__ float g_alpha_self[N_NODES * 4];
__device__ int   g_deg[N_NODES];
__device__ int   g_off[N_NODES + 1];
__device__ int   g_cur[N_NODES];
__device__ int   g_csrc[E_EDGES];

__device__ __forceinline__ float lrelu(float x) { return x >= 0.f ? x : LRELU_S * x; }

// ================= CSR build =================
__global__ void k_zero_deg() {
    int i = blockIdx.x * blockDim.x + threadIdx.x;
    if (i < N_NODES) g_deg[i] = 0;
}
__global__ void k_count_deg(const int* __restrict__ dst) {
    int e = blockIdx.x * blockDim.x + threadIdx.x;
    if (e < E_EDGES) atomicAdd(&g_deg[dst[e]], 1);
}
__global__ void k_scan_deg() {
    __shared__ int part[1024];
    int t = threadIdx.x;
    const int chunk = (N_NODES + 1023) / 1024;
    int s = 0;
    for (int i = 0; i < chunk; i++) {
        int idx = t * chunk + i;
        if (idx < N_NODES) s += g_deg[idx];
    }
    part[t] = s;
    __syncthreads();
    int val = s;
    for (int o = 1; o < 1024; o <<= 1) {
        int add = (t >= o) ? part[t - o] : 0;
        __syncthreads();
        val += add;
        part[t] = val;
        __syncthreads();
    }
    int base = val - s;
    for (int i = 0; i < chunk; i++) {
        int idx = t * chunk + i;
        if (idx < N_NODES) {
            g_off[idx] = base;
            g_cur[idx] = base;
            base += g_deg[idx];
        }
    }
    if (t == 0) g_off[N_NODES] = E_EDGES;
}
__global__ void k_scatter(const int* __restrict__ src, const int* __restrict__ dst) {
    int e = blockIdx.x * blockDim.x + threadIdx.x;
    if (e < E_EDGES) {
        int p = atomicAdd(&g_cur[dst[e]], 1);
        g_csrc[p] = src[e];
    }
}

// ================= converts =================
// Wt[n*K + k] = round_tf32(W[k*N + n])
__global__ void k_transp(const float* __restrict__ W, float* __restrict__ Wt, int K, int N) {
    int i = blockIdx.x * blockDim.x + threadIdx.x;
    if (i < K * N) {
        int k = i / N, n = i % N;
        Wt[(size_t)n * K + k] = round_tf32(W[i]);
    }
}

// ================= struct projection (sparse {0,1} matmul) -> tf32 =================
__global__ void k_struct_proj(const float* __restrict__ mh, const float* __restrict__ W,
                              const float* __restrict__ b, float* __restrict__ outB) {
    int warp = (blockIdx.x * blockDim.x + threadIdx.x) >> 5;
    int lane = threadIdx.x & 31;
    if (warp >= N_NODES) return;
    const float* row = mh + (size_t)warp * A_DIM;
    float a0 = 0.f, a1 = 0.f, a2 = 0.f, a3 = 0.f;
    for (int k0 = 0; k0 < A_DIM; k0 += 32) {
        int k = k0 + lane;
        float v = (k < A_DIM) ? row[k] : 0.f;
        unsigned m = __ballot_sync(0xffffffffu, v != 0.f);
        while (m) {
            int j = __ffs(m) - 1;
            m &= m - 1;
            float vj = __shfl_sync(0xffffffffu, v, j);
            const float* wr = W + (size_t)(k0 + j) * 128;
            a0 += wr[lane] * vj;
            a1 += wr[lane + 32] * vj;
            a2 += wr[lane + 64] * vj;
            a3 += wr[lane + 96] * vj;
        }
    }
    float* o = outB + (size_t)warp * 256;
    o[lane]      = round_tf32(a0 + b[lane]);
    o[lane + 32] = round_tf32(a1 + b[lane + 32]);
    o[lane + 64] = round_tf32(a2 + b[lane + 64]);
    o[lane + 96] = round_tf32(a3 + b[lane + 96]);
}

// ================= tf32 HMMA GEMM =================
// C[M, N] = A[M, K] @ Wt[N, K]^T   (tf32 in, fp32 acc)
// BM=128, BN=128, BK=32, 256 threads, 8 warps (2 m x 4 n), warp tile 64x32.
// OUT_MODE: 1 = fp32 tf32-rounded, 2 = bf16.  CVT_A: round A frags in-register.
// S=2 stages, 2 CTAs/SM. smem row stride 144B (conflict-free).
template <int OUT_MODE, bool CVT_A>
__global__ void __launch_bounds__(256, 2)
k_hgemm(const float* __restrict__ A, const float* __restrict__ Bt,
        void* __restrict__ Cv, int M, int K, int ldc, const float* __restrict__ bias) {
    constexpr int ROW_B = 144;
    constexpr int TILE_BYTES = 128 * ROW_B;      // 18432
    constexpr int STAGE = 2 * TILE_BYTES;

    extern __shared__ char smem[];
    uint32_t sb = smem_u32(smem);

    int tid = threadIdx.x;
    int wid = tid >> 5;
    int lane = tid & 31;
    int wm = wid & 1;
    int wn = wid >> 1;
    int bm = blockIdx.y * 128;
    int bn = blockIdx.x * 128;
    int KI = K / 32;

    int qrow = lane >> 2;
    int qk   = lane & 3;
    int qcol = qk * 2;

    float acc[4][4][4];
#pragma unroll
    for (int i = 0; i < 4; i++)
#pragma unroll
        for (int j = 0; j < 4; j++)
#pragma unroll
            for (int r = 0; r < 4; r++) acc[i][j][r] = 0.f;

    auto load_stage = [&](int kt, int s) {
        int k0 = kt * 32;
#pragma unroll
        for (int j = 0; j < 4; j++) {
            int ci = tid + j * 256;
            int row = ci >> 3, cp = ci & 7;
            uint32_t dst = sb + s * STAGE + row * ROW_B + cp * 16;
            if (bm + row < M)
                CP_ASYNC16(dst, A + (size_t)(bm + row) * K + k0 + cp * 4);
        }
#pragma unroll
        for (int j = 0; j < 4; j++) {
            int ci = tid + j * 256;
            int row = ci >> 3, cp = ci & 7;
            uint32_t dst = sb + s * STAGE + TILE_BYTES + row * ROW_B + cp * 16;
            CP_ASYNC16(dst, Bt + (size_t)(bn + row) * K + k0 + cp * 4);
        }
    };

    load_stage(0, 0); CP_COMMIT();
    if (KI > 1) load_stage(1, 1);
    CP_COMMIT();

    for (int kt = 0; kt < KI; kt++) {
        int s = kt & 1;
        CP_WAIT(1);
        __syncthreads();
        const char* As = smem + s * STAGE;
        const char* Bs = smem + s * STAGE + TILE_BYTES;
#pragma unroll
        for (int kk = 0; kk < 32; kk += 8) {
            uint32_t af[4][4], bf[4][2];
#pragma unroll
            for (int mt = 0; mt < 4; mt++) {
                int r0 = wm * 64 + mt * 16 + qrow;
                const char* p = As + r0 * ROW_B + (kk + qk) * 4;
                af[mt][0] = *reinterpret_cast<const uint32_t*>(p);
                af[mt][1] = *reinterpret_cast<const uint32_t*>(p + 8 * ROW_B);
                af[mt][2] = *reinterpret_cast<const uint32_t*>(p + 16);
                af[mt][3] = *reinterpret_cast<const uint32_t*>(p + 8 * ROW_B + 16);
                if (CVT_A) {
#pragma unroll
                    for (int i = 0; i < 4; i++) af[mt][i] = round_tf32_u(af[mt][i]);
                }
            }
#pragma unroll
            for (int nt = 0; nt < 4; nt++) {
                int n0 = wn * 32 + nt * 8 + qrow;
                const char* p = Bs + n0 * ROW_B + (kk + qk) * 4;
                bf[nt][0] = *reinterpret_cast<const uint32_t*>(p);
                bf[nt][1] = *reinterpret_cast<const uint32_t*>(p + 16);
            }
#pragma unroll
            for (int mt = 0; mt < 4; mt++)
#pragma unroll
                for (int nt = 0; nt < 4; nt++)
                    mma_tf32(acc[mt][nt][0], acc[mt][nt][1], acc[mt][nt][2], acc[mt][nt][3],
                             af[mt][0], af[mt][1], af[mt][2], af[mt][3],
                             bf[nt][0], bf[nt][1]);
        }
        __syncthreads();
        int kn = kt + 2;
        if (kn < KI) load_stage(kn, s);
        CP_COMMIT();
    }

    // ---- epilogue ----
#pragma unroll
    for (int mt = 0; mt < 4; mt++) {
        int r0 = bm + wm * 64 + mt * 16 + qrow;
#pragma unroll
        for (int nt = 0; nt < 4; nt++) {
            int c = bn + wn * 32 + nt * 8 + qcol;
            float v0 = acc[mt][nt][0], v1 = acc[mt][nt][1];
            float v2 = acc[mt][nt][2], v3 = acc[mt][nt][3];
            if (bias) {
                float b0 = bias[c], b1 = bias[c + 1];
                v0 += b0; v1 += b1; v2 += b0; v3 += b1;
            }
            if (OUT_MODE == 2) {
                __nv_bfloat16* C = (__nv_bfloat16*)Cv;
                if (r0 < M)
                    *reinterpret_cast<__nv_bfloat162*>(C + (size_t)r0 * ldc + c) = __floats2bfloat162_rn(v0, v1);
                if (r0 + 8 < M)
                    *reinterpret_cast<__nv_bfloat162*>(C + (size_t)(r0 + 8) * ldc + c) = __floats2bfloat162_rn(v2, v3);
            } else {
                float* C = (float*)Cv;
                v0 = round_tf32(v0); v1 = round_tf32(v1);
                v2 = round_tf32(v2); v3 = round_tf32(v3);
                if (r0 < M)
                    *reinterpret_cast<float2*>(C + (size_t)r0 * ldc + c) = make_float2(v0, v1);
                if (r0 + 8 < M)
                    *reinterpret_cast<float2*>(C + (size_t)(r0 + 8) * ldc + c) = make_float2(v2, v3);
            }
        }
    }
}

// ================= attention scores (bf16 xl) =================
template <int H, int C>
__global__ void k_att_prep(const __nv_bfloat16* __restrict__ xl, const float* __restrict__ att_src,
                           const float* __restrict__ att_dst) {
    int warp = (blockIdx.x * blockDim.x + threadIdx.x) >> 5;
    int lane = threadIdx.x & 31;
    if (warp >= N_NODES * H) return;
    int n = warp / H, h = warp % H;
    const __nv_bfloat16* row = xl + (size_t)n * (H * C) + h * C;
    float s = 0.f, d = 0.f;
#pragma unroll
    for (int i = 0; i < C / 64; i++) {
        int c = i * 64 + lane * 2;
        float2 v = __bfloat1622float2(*reinterpret_cast<const __nv_bfloat162*>(row + c));
        s += v.x * att_src[h * C + c] + v.y * att_src[h * C + c + 1];
        d += v.x * att_dst[h * C + c] + v.y * att_dst[h * C + c + 1];
    }
#pragma unroll
    for (int o = 16; o; o >>= 1) {
        s += __shfl_down_sync(0xffffffffu, s, o);
        d += __shfl_down_sync(0xffffffffu, d, o);
    }
    if (lane == 0) {
        g_asrc[n * H + h] = s;
        g_adst[n * H + h] = d;
    }
}

template <int H>
__global__ void k_attention() {
    int idx = blockIdx.x * blockDim.x + threadIdx.x;
    if (idx >= N_NODES * H) return;
    int n = idx / H, h = idx % H;
    float ad = g_adst[n * H + h];
    int s0 = g_off[n], s1 = g_off[n + 1];
    float eself = lrelu(g_asrc[n * H + h] + ad);
    float mx = eself;
    for (int s = s0; s < s1; s++) {
        float e = lrelu(g_asrc[g_csrc[s] * H + h] + ad);
        mx = fmaxf(mx, e);
    }
    float denom = __expf(eself - mx);
    for (int s = s0; s < s1; s++) {
        float e = lrelu(g_asrc[g_csrc[s] * H + h] + ad);
        denom += __expf(e - mx);
    }
    float inv = 1.f / (denom + 1e-16f);
    g_alpha_self[n * H + h] = __expf(eself - mx) * inv;
    for (int s = s0; s < s1; s++) {
        float e = lrelu(g_asrc[g_csrc[s] * H + h] + ad);
        g_alpha[(size_t)s * H + h] = __expf(e - mx) * inv;
    }
}

// ================= aggregation (bf16 xl in, fp32 out) =================
// gat1: H=2, C=128, head-mean. 64 threads; thread t -> cols 2t, 2t+1. ROUND out.
__global__ void k_agg_mean_2_128(const __nv_bfloat16* __restrict__ xl,
                                 const float* __restrict__ bias, float* __restrict__ out) {
    int n = blockIdx.x;
    int t = threadIdx.x;     // 0..63
    int s0 = g_off[n], s1 = g_off[n + 1];
    float a0 = 0.f, a1 = 0.f;
#pragma unroll
    for (int h = 0; h < 2; h++) {
        float al = g_alpha_self[n * 2 + h];
        float2 v = __bfloat1622float2(
            *reinterpret_cast<const __nv_bfloat162*>(xl + (size_t)n * 256 + h * 128 + 2 * t));
        a0 += al * v.x; a1 += al * v.y;
    }
    for (int s = s0; s < s1; s++) {
        int src = g_csrc[s];
#pragma unroll
        for (int h = 0; h < 2; h++) {
            float al = g_alpha[(size_t)s * 2 + h];
            float2 v = __bfloat1622float2(
                *reinterpret_cast<const __nv_bfloat162*>(xl + (size_t)src * 256 + h * 128 + 2 * t));
            a0 += al * v.x; a1 += al * v.y;
        }
    }
    float2 o = make_float2(round_tf32(a0 * 0.5f + bias[2 * t]),
                           round_tf32(a1 * 0.5f + bias[2 * t + 1]));
    *reinterpret_cast<float2*>(out + (size_t)n * 128 + 2 * t) = o;
}

// gat2: H=4, C=256, concat + relu. 256 threads; thread t -> cols 4t..4t+3, head t/64.
__global__ void k_agg_concat_relu(const __nv_bfloat16* __restrict__ xl,
                                  const float* __restrict__ bias, float* __restrict__ out) {
    int n = blockIdx.x;
    int t = threadIdx.x;     // 0..255
    int j = t >> 6;          // head
    int c0 = 4 * t;
    int s0 = g_off[n], s1 = g_off[n + 1];
    float a0, a1, a2, a3;
    {
        float al = g_alpha_self[n * 4 + j];
        uint2 u = *reinterpret_cast<const uint2*>(xl + (size_t)n * 1024 + c0);
        float2 p = __bfloat1622float2(*reinterpret_cast<__nv_bfloat162*>(&u.x));
        float2 q = __bfloat1622float2(*reinterpret_cast<__nv_bfloat162*>(&u.y));
        a0 = al * p.x; a1 = al * p.y; a2 = al * q.x; a3 = al * q.y;
    }
    for (int s = s0; s < s1; s++) {
        int src = g_csrc[s];
        float al = g_alpha[(size_t)s * 4 + j];
        uint2 u = *reinterpret_cast<const uint2*>(xl + (size_t)src * 1024 + c0);
        float2 p = __bfloat1622float2(*reinterpret_cast<__nv_bfloat162*>(&u.x));
        float2 q = __bfloat1622float2(*reinterpret_cast<__nv_bfloat162*>(&u.y));
        a0 += al * p.x; a1 += al * p.y; a2 += al * q.x; a3 += al * q.y;
    }
    float4 o;
    o.x = round_tf32(fmaxf(a0 + bias[c0], 0.f));
    o.y = round_tf32(fmaxf(a1 + bias[c0 + 1], 0.f));
    o.z = round_tf32(fmaxf(a2 + bias[c0 + 2], 0.f));
    o.w = round_tf32(fmaxf(a3 + bias[c0 + 3], 0.f));
    *reinterpret_cast<float4*>(out + (size_t)n * 1024 + c0) = o;
}

// gat3: H=4, C=256, head-mean. 128 threads; thread t -> cols 2t, 2t+1. fp32 out (no round).
__global__ void k_agg_mean_4_256(const __nv_bfloat16* __restrict__ xl,
                                 const float* __restrict__ bias, float* __restrict__ out) {
    int n = blockIdx.x;
    int t = threadIdx.x;     // 0..127
    int s0 = g_off[n], s1 = g_off[n + 1];
    float a0 = 0.f, a1 = 0.f;
#pragma unroll
    for (int h = 0; h < 4; h++) {
        float al = g_alpha_self[n * 4 + h];
        float2 v = __bfloat1622float2(
            *reinterpret_cast<const __nv_bfloat162*>(xl + (size_t)n * 1024 + h * 256 + 2 * t));
        a0 += al * v.x; a1 += al * v.y;
    }
    for (int s = s0; s < s1; s++) {
        int src = g_csrc[s];
        const __nv_bfloat16* xr = xl + (size_t)src * 1024 + 2 * t;
#pragma unroll
        for (int h = 0; h < 4; h++) {
            float al = g_alpha[(size_t)s * 4 + h];
            float2 v = __bfloat1622float2(
                *reinterpret_cast<const __nv_bfloat162*>(xr + h * 256));
            a0 += al * v.x; a1 += al * v.y;
        }
    }
    float2 o = make_float2(a0 * 0.25f + bias[2 * t], a1 * 0.25f + bias[2 * t + 1]);
    *reinterpret_cast<float2*>(out + (size_t)n * 256 + 2 * t) = o;
}

// ================= double layernorm (C=256) =================
__global__ void k_double_ln(float* __restrict__ x,
                            const float* __restrict__ g1, const float* __restrict__ b1,
                            const float* __restrict__ g2, const float* __restrict__ b2) {
    __shared__ float sh[256];
    int n = blockIdx.x, t = threadIdx.x;
    float v = x[(size_t)n * 256 + t];

    sh[t] = v; __syncthreads();
    for (int o = 128; o; o >>= 1) { if (t < o) sh[t] += sh[t + o]; __syncthreads(); }
    float mu = sh[0] * (1.f / 256.f); __syncthreads();
    float d = v - mu;
    sh[t] = d * d; __syncthreads();
    for (int o = 128; o; o >>= 1) { if (t < o) sh[t] += sh[t + o]; __syncthreads(); }
    float var = sh[0] * (1.f / 256.f); __syncthreads();
    v = d * rsqrtf(var + 1e-5f) * g1[t] + b1[t];

    sh[t] = v; __syncthreads();
    for (int o = 128; o; o >>= 1) { if (t < o) sh[t] += sh[t + o]; __syncthreads(); }
    mu = sh[0] * (1.f / 256.f); __syncthreads();
    d = v - mu;
    sh[t] = d * d; __syncthreads();
    for (int o = 128; o; o >>= 1) { if (t < o) sh[t] += sh[t + o]; __syncthreads(); }
    var = sh[0] * (1.f / 256.f); __syncthreads();
    v = d * rsqrtf(var + 1e-5f) * g2[t] + b2[t];

    x[(size_t)n * 256 + t] = v;
}

// ================= mean pool =================
__global__ void k_zero_out(float* out) { out[threadIdx.x] = 0.f; }
__global__ void k_pool(const float* __restrict__ x, float* __restrict__ out) {
    int t = threadIdx.x;
    int b = blockIdx.x;
    int rows_per = (N_NODES + gridDim.x - 1) / gridDim.x;
    int r0 = b * rows_per;
    int r1 = min(r0 + rows_per, N_NODES);
    float acc = 0.f;
    for (int r = r0; r < r1; r++) acc += x[(size_t)r * 256 + t];
    atomicAdd(&out[t], acc * (1.f / (float)N_NODES));
}

// ================= launch =================
extern "C" void kernel_launch(void* const* d_in, const int* in_sizes, int n_in,
                              void* d_out, int out_size) {
    const float* multi_hot = (const float*)d_in[0];
    const float* bert_feat = (const float*)d_in[1];
    const int*   edge      = (const int*)d_in[2];
    const float* W_struct  = (const float*)d_in[3];
    const float* b_struct  = (const float*)d_in[4];
    const float* W_bert    = (const float*)d_in[5];
    const float* b_bert    = (const float*)d_in[6];
    const float* W_g1      = (const float*)d_in[7];
    const float* att_src1  = (const float*)d_in[8];
    const float* att_dst1  = (const float*)d_in[9];
    const float* b_g1      = (const float*)d_in[10];
    const float* W_g2      = (const float*)d_in[11];
    const float* att_src2  = (const float*)d_in[12];
    const float* att_dst2  = (const float*)d_in[13];
    const float* b_g2      = (const float*)d_in[14];
    const float* W_g3      = (const float*)d_in[15];
    const float* att_src3  = (const float*)d_in[16];
    const float* att_dst3  = (const float*)d_in[17];
    const float* b_g3      = (const float*)d_in[18];
    const float* ln1_g     = (const float*)d_in[19];
    const float* ln1_b     = (const float*)d_in[20];
    const float* ln2_g     = (const float*)d_in[21];
    const float* ln2_b     = (const float*)d_in[22];
    float* out = (float*)d_out;

    const int* e_src = edge;
    const int* e_dst = edge + E_EDGES;

    float *B2, *fused, *x1, *x2, *Wt;
    __nv_bfloat16* xl;
    cudaGetSymbolAddress((void**)&xl, g_xl);
    cudaGetSymbolAddress((void**)&B2, g_B2);
    cudaGetSymbolAddress((void**)&fused, g_fused);
    cudaGetSymbolAddress((void**)&x1, g_x1);
    cudaGetSymbolAddress((void**)&x2, g_x2);
    cudaGetSymbolAddress((void**)&Wt, g_Wt);

    const int SMEM = 2 * 2 * 128 * 144;   // 73728
    cudaFuncSetAttribute(k_hgemm<1, true>,  cudaFuncAttributeMaxDynamicSharedMemorySize, SMEM);
    cudaFuncSetAttribute(k_hgemm<2, false>, cudaFuncAttributeMaxDynamicSharedMemorySize, SMEM);

    const int MB = (N_NODES + 127) / 128;   // 391

    // --- CSR build ---
    k_zero_deg<<<(N_NODES + 255) / 256, 256>>>();
    k_count_deg<<<(E_EDGES + 255) / 256, 256>>>(e_dst);
    k_scan_deg<<<1, 1024>>>();
    k_scatter<<<(E_EDGES + 255) / 256, 256>>>(e_src, e_dst);

    // --- fused features (fp32/tf32) ---
    k_struct_proj<<<(N_NODES + 7) / 8, 256>>>(multi_hot, W_struct, b_struct, fused);
    k_transp<<<(768 * 128 + 255) / 256, 256>>>(W_bert, Wt, 768, 128);
    k_hgemm<1, true><<<dim3(1, MB), 256, SMEM>>>(bert_feat, Wt, fused + 128, N_NODES, 768, 256, b_bert);

    // --- GAT1: 256 -> (2,128) mean -> 128 ---
    k_transp<<<(256 * 256 + 255) / 256, 256>>>(W_g1, Wt, 256, 256);
    k_hgemm<2, false><<<dim3(2, MB), 256, SMEM>>>(fused, Wt, xl, N_NODES, 256, 256, nullptr);
    k_att_prep<2, 128><<<(N_NODES * 2 + 7) / 8, 256>>>(xl, att_src1, att_dst1);
    k_attention<2><<<(N_NODES * 2 + 255) / 256, 256>>>();
    k_agg_mean_2_128<<<N_NODES, 64>>>(xl, b_g1, x1);

    // --- GAT2: 128 -> (4,256) concat -> 1024, relu ---
    k_transp<<<(128 * 1024 + 255) / 256, 256>>>(W_g2, Wt, 128, 1024);
    k_hgemm<2, false><<<dim3(8, MB), 256, SMEM>>>(x1, Wt, xl, N_NODES, 128, 1024, nullptr);
    k_att_prep<4, 256><<<(N_NODES * 4 + 7) / 8, 256>>>(xl, att_src2, att_dst2);
    k_attention<4><<<(N_NODES * 4 + 255) / 256, 256>>>();
    k_agg_concat_relu<<<N_NODES, 256>>>(xl, b_g2, x2);

    // --- GAT3: 1024 -> (4,256) mean -> 256 ---
    k_transp<<<(1024 * 1024 + 255) / 256, 256>>>(W_g3, Wt, 1024, 1024);
    k_hgemm<2, false><<<dim3(8, MB), 256, SMEM>>>(x2, Wt, xl, N_NODES, 1024, 1024, nullptr);
    k_att_prep<4, 256><<<(N_NODES * 4 + 7) / 8, 256>>>(xl, att_src3, att_dst3);
    k_attention<4><<<(N_NODES * 4 + 255) / 256, 256>>>();
    k_agg_mean_4_256<<<N_NODES, 128>>>(xl, b_g3, B2);

    // --- double LN + mean pool ---
    k_double_ln<<<N_NODES, 256>>>(B2, ln1_g, ln1_b, ln2_g, ln2_b);
    k_zero_out<<<1, 256>>>(out);
    k_pool<<<200, 256>>>(B2, out);
}

// round 9
// speedup vs baseline: 3.2028x; 1.2924x over previous
#include <cuda_runtime.h>
#include <cuda_fp16.h>
#include <math.h>
#include <stdint.h>

#define N_NODES 50000
#define E_EDGES 200000
#define A_DIM   2000
#define LRELU_S 0.2f

// ================= helpers =================
__device__ __forceinline__ uint32_t smem_u32(const void* p) {
    uint32_t a;
    asm("{ .reg .u64 t; cvta.to.shared.u64 t, %1; cvt.u32.u64 %0, t; }" : "=r"(a) : "l"(p));
    return a;
}
#define CP_ASYNC16(dst, src) \
    asm volatile("cp.async.cg.shared.global [%0], [%1], 16;" :: "r"((uint32_t)(dst)), "l"(src) : "memory")
#define CP_COMMIT() asm volatile("cp.async.commit_group;" ::: "memory")
#define CP_WAIT(n)  asm volatile("cp.async.wait_group %0;" :: "n"(n) : "memory")

__device__ __forceinline__ void mma16816(float& c0, float& c1, float& c2, float& c3,
                                         uint32_t a0, uint32_t a1, uint32_t a2, uint32_t a3,
                                         uint32_t b0, uint32_t b1) {
    asm volatile("mma.sync.aligned.m16n8k16.row.col.f32.f16.f16.f32 "
                 "{%0,%1,%2,%3}, {%4,%5,%6,%7}, {%8,%9}, {%0,%1,%2,%3};"
                 : "+f"(c0), "+f"(c1), "+f"(c2), "+f"(c3)
                 : "r"(a0), "r"(a1), "r"(a2), "r"(a3), "r"(b0), "r"(b1));
}

// ================= scratch (static globals) =================
__device__ __half g_xl[(size_t)N_NODES * 1024];     // GEMM fp16 out
__device__ float  g_B2[(size_t)N_NODES * 256];      // gat3 agg out (fp32, feeds LN)
__device__ __half g_bert[(size_t)N_NODES * 768];    // fp16 bert
__device__ __half g_fused[(size_t)N_NODES * 256];   // fp16 fused features
__device__ __half g_x1[(size_t)N_NODES * 128];      // fp16 gat1 agg
__device__ __half g_x2[(size_t)N_NODES * 1024];     // fp16 gat2 agg (relu)
__device__ __half g_Wt[1024 * 1024];                // fp16 transposed weights
__device__ float g_asrc[N_NODES * 4];
__device__ float g_adst[N_NODES * 4];
__device__ float g_alpha[(size_t)E_EDGES * 4];
__device__ float g_alpha_self[N_NODES * 4];
__device__ int   g_deg[N_NODES];
__device__ int   g_off[N_NODES + 1];
__device__ int   g_cur[N_NODES];
__device__ int   g_csrc[E_EDGES];

__device__ __forceinline__ float lrelu(float x) { return x >= 0.f ? x : LRELU_S * x; }

// ================= CSR build =================
__global__ void k_zero_deg() {
    int i = blockIdx.x * blockDim.x + threadIdx.x;
    if (i < N_NODES) g_deg[i] = 0;
}
__global__ void k_count_deg(const int* __restrict__ dst) {
    int e = blockIdx.x * blockDim.x + threadIdx.x;
    if (e < E_EDGES) atomicAdd(&g_deg[dst[e]], 1);
}
__global__ void k_scan_deg() {
    __shared__ int part[1024];
    int t = threadIdx.x;
    const int chunk = (N_NODES + 1023) / 1024;
    int s = 0;
    for (int i = 0; i < chunk; i++) {
        int idx = t * chunk + i;
        if (idx < N_NODES) s += g_deg[idx];
    }
    part[t] = s;
    __syncthreads();
    int val = s;
    for (int o = 1; o < 1024; o <<= 1) {
        int add = (t >= o) ? part[t - o] : 0;
        __syncthreads();
        val += add;
        part[t] = val;
        __syncthreads();
    }
    int base = val - s;
    for (int i = 0; i < chunk; i++) {
        int idx = t * chunk + i;
        if (idx < N_NODES) {
            g_off[idx] = base;
            g_cur[idx] = base;
            base += g_deg[idx];
        }
    }
    if (t == 0) g_off[N_NODES] = E_EDGES;
}
__global__ void k_scatter(const int* __restrict__ src, const int* __restrict__ dst) {
    int e = blockIdx.x * blockDim.x + threadIdx.x;
    if (e < E_EDGES) {
        int p = atomicAdd(&g_cur[dst[e]], 1);
        g_csrc[p] = src[e];
    }
}

// ================= converts =================
__global__ void k_f32_to_f16(const float* __restrict__ in, __half* __restrict__ out, size_t n4) {
    size_t i = (size_t)blockIdx.x * blockDim.x + threadIdx.x;
    if (i < n4) {
        float4 v = reinterpret_cast<const float4*>(in)[i];
        __half2 h0 = __floats2half2_rn(v.x, v.y);
        __half2 h1 = __floats2half2_rn(v.z, v.w);
        uint2 u;
        u.x = *reinterpret_cast<uint32_t*>(&h0);
        u.y = *reinterpret_cast<uint32_t*>(&h1);
        reinterpret_cast<uint2*>(out)[i] = u;
    }
}
// Tiled transpose: Wt[n*K + k] = (half)W[k*N + n]. K, N multiples of 32.
__global__ void k_transp(const float* __restrict__ W, __half* __restrict__ Wt, int K, int N) {
    __shared__ float tile[32][33];
    int k0 = blockIdx.y * 32, n0 = blockIdx.x * 32;
    int tx = threadIdx.x, ty = threadIdx.y;   // block 32x8
#pragma unroll
    for (int i = 0; i < 32; i += 8)
        tile[ty + i][tx] = W[(size_t)(k0 + ty + i) * N + n0 + tx];
    __syncthreads();
#pragma unroll
    for (int i = 0; i < 32; i += 8)
        Wt[(size_t)(n0 + ty + i) * K + k0 + tx] = __float2half(tile[tx][ty + i]);
}

// ================= struct projection (sparse {0,1} matmul) -> fp16 =================
__global__ void k_struct_proj(const float* __restrict__ mh, const float* __restrict__ W,
                              const float* __restrict__ b, __half* __restrict__ outB) {
    int warp = (blockIdx.x * blockDim.x + threadIdx.x) >> 5;
    int lane = threadIdx.x & 31;
    if (warp >= N_NODES) return;
    const float* row = mh + (size_t)warp * A_DIM;
    float a0 = 0.f, a1 = 0.f, a2 = 0.f, a3 = 0.f;
    for (int k0 = 0; k0 < A_DIM; k0 += 32) {
        int k = k0 + lane;
        float v = (k < A_DIM) ? row[k] : 0.f;
        unsigned m = __ballot_sync(0xffffffffu, v != 0.f);
        while (m) {
            int j = __ffs(m) - 1;
            m &= m - 1;
            float vj = __shfl_sync(0xffffffffu, v, j);
            const float* wr = W + (size_t)(k0 + j) * 128;
            a0 += wr[lane] * vj;
            a1 += wr[lane + 32] * vj;
            a2 += wr[lane + 64] * vj;
            a3 += wr[lane + 96] * vj;
        }
    }
    __half* o = outB + (size_t)warp * 256;
    o[lane]      = __float2half(a0 + b[lane]);
    o[lane + 32] = __float2half(a1 + b[lane + 32]);
    o[lane + 64] = __float2half(a2 + b[lane + 64]);
    o[lane + 96] = __float2half(a3 + b[lane + 96]);
}

// ================= fp16 HMMA GEMM =================
// C[M, N] = A[M, K] @ Wt[N, K]^T  (fp16 in, fp32 acc, fp16 out)
// BM=128, BN=128, BK=32, 256 threads, 8 warps (2 m x 4 n), warp tile 64x32.
// S=3 stages, 2 CTAs/SM. smem row stride 80B (conflict-free).
__global__ void __launch_bounds__(256, 2)
k_hgemm(const __half* __restrict__ A, const __half* __restrict__ Bt,
        __half* __restrict__ C, int M, int K, int ldc, const float* __restrict__ bias) {
    constexpr int S = 3;
    constexpr int TILE_BYTES = 128 * 80;
    constexpr int STAGE = 2 * TILE_BYTES;

    extern __shared__ char smem[];
    uint32_t sb = smem_u32(smem);

    int tid = threadIdx.x;
    int wid = tid >> 5;
    int lane = tid & 31;
    int wm = wid & 1;
    int wn = wid >> 1;
    int bm = blockIdx.y * 128;
    int bn = blockIdx.x * 128;
    int KI = K / 32;

    int qrow = lane >> 2;
    int qcol = (lane & 3) * 2;

    float acc[4][4][4];
#pragma unroll
    for (int i = 0; i < 4; i++)
#pragma unroll
        for (int j = 0; j < 4; j++)
#pragma unroll
            for (int r = 0; r < 4; r++) acc[i][j][r] = 0.f;

    auto load_stage = [&](int kt, int s) {
        int k0 = kt * 32;
#pragma unroll
        for (int j = 0; j < 2; j++) {
            int ci = tid + j * 256;
            int row = ci >> 2, cp = ci & 3;
            uint32_t dst = sb + s * STAGE + row * 80 + cp * 16;
            if (bm + row < M)
                CP_ASYNC16(dst, A + (size_t)(bm + row) * K + k0 + cp * 8);
        }
#pragma unroll
        for (int j = 0; j < 2; j++) {
            int ci = tid + j * 256;
            int row = ci >> 2, cp = ci & 3;
            uint32_t dst = sb + s * STAGE + TILE_BYTES + row * 80 + cp * 16;
            CP_ASYNC16(dst, Bt + (size_t)(bn + row) * K + k0 + cp * 8);
        }
    };

    load_stage(0, 0); CP_COMMIT();
    if (KI > 1) load_stage(1, 1);
    CP_COMMIT();

    for (int kt = 0; kt < KI; kt++) {
        int s = kt % S;
        CP_WAIT(1);
        __syncthreads();
        const char* As = smem + s * STAGE;
        const char* Bs = smem + s * STAGE + TILE_BYTES;
#pragma unroll
        for (int kk = 0; kk < 32; kk += 16) {
            uint32_t af[4][4], bf[4][2];
#pragma unroll
            for (int mt = 0; mt < 4; mt++) {
                int r0 = wm * 64 + mt * 16 + qrow;
                const char* p = As + r0 * 80 + (kk + qcol) * 2;
                af[mt][0] = *reinterpret_cast<const uint32_t*>(p);
                af[mt][1] = *reinterpret_cast<const uint32_t*>(p + 8 * 80);
                af[mt][2] = *reinterpret_cast<const uint32_t*>(p + 16);
                af[mt][3] = *reinterpret_cast<const uint32_t*>(p + 8 * 80 + 16);
            }
#pragma unroll
            for (int nt = 0; nt < 4; nt++) {
                int n0 = wn * 32 + nt * 8 + qrow;
                const char* p = Bs + n0 * 80 + (kk + qcol) * 2;
                bf[nt][0] = *reinterpret_cast<const uint32_t*>(p);
                bf[nt][1] = *reinterpret_cast<const uint32_t*>(p + 16);
            }
#pragma unroll
            for (int mt = 0; mt < 4; mt++)
#pragma unroll
                for (int nt = 0; nt < 4; nt++)
                    mma16816(acc[mt][nt][0], acc[mt][nt][1], acc[mt][nt][2], acc[mt][nt][3],
                             af[mt][0], af[mt][1], af[mt][2], af[mt][3],
                             bf[nt][0], bf[nt][1]);
        }
        int kn = kt + 2;
        if (kn < KI) load_stage(kn, kn % S);
        CP_COMMIT();
    }

    // ---- epilogue (fp16 out) ----
#pragma unroll
    for (int mt = 0; mt < 4; mt++) {
        int r0 = bm + wm * 64 + mt * 16 + qrow;
#pragma unroll
        for (int nt = 0; nt < 4; nt++) {
            int c = bn + wn * 32 + nt * 8 + qcol;
            float v0 = acc[mt][nt][0], v1 = acc[mt][nt][1];
            float v2 = acc[mt][nt][2], v3 = acc[mt][nt][3];
            if (bias) {
                float b0 = bias[c], b1 = bias[c + 1];
                v0 += b0; v1 += b1; v2 += b0; v3 += b1;
            }
            if (r0 < M)
                *reinterpret_cast<__half2*>(C + (size_t)r0 * ldc + c) = __floats2half2_rn(v0, v1);
            if (r0 + 8 < M)
                *reinterpret_cast<__half2*>(C + (size_t)(r0 + 8) * ldc + c) = __floats2half2_rn(v2, v3);
        }
    }
}

// ================= attention scores (fp16 xl) =================
template <int H, int C>
__global__ void k_att_prep(const __half* __restrict__ xl, const float* __restrict__ att_src,
                           const float* __restrict__ att_dst) {
    int warp = (blockIdx.x * blockDim.x + threadIdx.x) >> 5;
    int lane = threadIdx.x & 31;
    if (warp >= N_NODES * H) return;
    int n = warp / H, h = warp % H;
    const __half* row = xl + (size_t)n * (H * C) + h * C;
    float s = 0.f, d = 0.f;
#pragma unroll
    for (int i = 0; i < C / 64; i++) {
        int c = i * 64 + lane * 2;
        float2 v = __half22float2(*reinterpret_cast<const __half2*>(row + c));
        s += v.x * att_src[h * C + c] + v.y * att_src[h * C + c + 1];
        d += v.x * att_dst[h * C + c] + v.y * att_dst[h * C + c + 1];
    }
#pragma unroll
    for (int o = 16; o; o >>= 1) {
        s += __shfl_down_sync(0xffffffffu, s, o);
        d += __shfl_down_sync(0xffffffffu, d, o);
    }
    if (lane == 0) {
        g_asrc[n * H + h] = s;
        g_adst[n * H + h] = d;
    }
}

template <int H>
__global__ void k_attention() {
    int idx = blockIdx.x * blockDim.x + threadIdx.x;
    if (idx >= N_NODES * H) return;
    int n = idx / H, h = idx % H;
    float ad = g_adst[n * H + h];
    int s0 = g_off[n], s1 = g_off[n + 1];
    float eself = lrelu(g_asrc[n * H + h] + ad);
    float mx = eself;
    for (int s = s0; s < s1; s++) {
        float e = lrelu(g_asrc[g_csrc[s] * H + h] + ad);
        mx = fmaxf(mx, e);
    }
    float denom = __expf(eself - mx);
    for (int s = s0; s < s1; s++) {
        float e = lrelu(g_asrc[g_csrc[s] * H + h] + ad);
        denom += __expf(e - mx);
    }
    float inv = 1.f / (denom + 1e-16f);
    g_alpha_self[n * H + h] = __expf(eself - mx) * inv;
    for (int s = s0; s < s1; s++) {
        float e = lrelu(g_asrc[g_csrc[s] * H + h] + ad);
        g_alpha[(size_t)s * H + h] = __expf(e - mx) * inv;
    }
}

// ================= aggregation (fp16 xl in) =================
// gat1: H=2, C=128, head-mean -> fp16. 64 threads; t -> cols 2t, 2t+1.
__global__ void k_agg_mean_2_128(const __half* __restrict__ xl,
                                 const float* __restrict__ bias, __half* __restrict__ out) {
    int n = blockIdx.x;
    int t = threadIdx.x;
    int s0 = g_off[n], s1 = g_off[n + 1];
    float a0 = 0.f, a1 = 0.f;
#pragma unroll
    for (int h = 0; h < 2; h++) {
        float al = g_alpha_self[n * 2 + h];
        float2 v = __half22float2(
            *reinterpret_cast<const __half2*>(xl + (size_t)n * 256 + h * 128 + 2 * t));
        a0 += al * v.x; a1 += al * v.y;
    }
    for (int s = s0; s < s1; s++) {
        int src = g_csrc[s];
#pragma unroll
        for (int h = 0; h < 2; h++) {
            float al = g_alpha[(size_t)s * 2 + h];
            float2 v = __half22float2(
                *reinterpret_cast<const __half2*>(xl + (size_t)src * 256 + h * 128 + 2 * t));
            a0 += al * v.x; a1 += al * v.y;
        }
    }
    *reinterpret_cast<__half2*>(out + (size_t)n * 128 + 2 * t) =
        __floats2half2_rn(a0 * 0.5f + bias[2 * t], a1 * 0.5f + bias[2 * t + 1]);
}

// gat2: H=4, C=256, concat + relu -> fp16. 256 threads; t -> cols 4t..4t+3, head t/64.
__global__ void k_agg_concat_relu(const __half* __restrict__ xl,
                                  const float* __restrict__ bias, __half* __restrict__ out) {
    int n = blockIdx.x;
    int t = threadIdx.x;
    int j = t >> 6;
    int c0 = 4 * t;
    int s0 = g_off[n], s1 = g_off[n + 1];
    float a0, a1, a2, a3;
    {
        float al = g_alpha_self[n * 4 + j];
        uint2 u = *reinterpret_cast<const uint2*>(xl + (size_t)n * 1024 + c0);
        float2 p = __half22float2(*reinterpret_cast<__half2*>(&u.x));
        float2 q = __half22float2(*reinterpret_cast<__half2*>(&u.y));
        a0 = al * p.x; a1 = al * p.y; a2 = al * q.x; a3 = al * q.y;
    }
    for (int s = s0; s < s1; s++) {
        int src = g_csrc[s];
        float al = g_alpha[(size_t)s * 4 + j];
        uint2 u = *reinterpret_cast<const uint2*>(xl + (size_t)src * 1024 + c0);
        float2 p = __half22float2(*reinterpret_cast<__half2*>(&u.x));
        float2 q = __half22float2(*reinterpret_cast<__half2*>(&u.y));
        a0 += al * p.x; a1 += al * p.y; a2 += al * q.x; a3 += al * q.y;
    }
    __half2 h0 = __floats2half2_rn(fmaxf(a0 + bias[c0], 0.f),     fmaxf(a1 + bias[c0 + 1], 0.f));
    __half2 h1 = __floats2half2_rn(fmaxf(a2 + bias[c0 + 2], 0.f), fmaxf(a3 + bias[c0 + 3], 0.f));
    uint2 u;
    u.x = *reinterpret_cast<uint32_t*>(&h0);
    u.y = *reinterpret_cast<uint32_t*>(&h1);
    *reinterpret_cast<uint2*>(out + (size_t)n * 1024 + c0) = u;
}

// gat3: H=4, C=256, head-mean -> fp32 (feeds LN). 128 threads; t -> cols 2t, 2t+1.
__global__ void k_agg_mean_4_256(const __half* __restrict__ xl,
                                 const float* __restrict__ bias, float* __restrict__ out) {
    int n = blockIdx.x;
    int t = threadIdx.x;
    int s0 = g_off[n], s1 = g_off[n + 1];
    float a0 = 0.f, a1 = 0.f;
#pragma unroll
    for (int h = 0; h < 4; h++) {
        float al = g_alpha_self[n * 4 + h];
        float2 v = __half22float2(
            *reinterpret_cast<const __half2*>(xl + (size_t)n * 1024 + h * 256 + 2 * t));
        a0 += al * v.x; a1 += al * v.y;
    }
    for (int s = s0; s < s1; s++) {
        int src = g_csrc[s];
        const __half* xr = xl + (size_t)src * 1024 + 2 * t;
#pragma unroll
        for (int h = 0; h < 4; h++) {
            float al = g_alpha[(size_t)s * 4 + h];
            float2 v = __half22float2(*reinterpret_cast<const __half2*>(xr + h * 256));
            a0 += al * v.x; a1 += al * v.y;
        }
    }
    *reinterpret_cast<float2*>(out + (size_t)n * 256 + 2 * t) =
        make_float2(a0 * 0.25f + bias[2 * t], a1 * 0.25f + bias[2 * t + 1]);
}

// ================= double layernorm (C=256) =================
__global__ void k_double_ln(float* __restrict__ x,
                            const float* __restrict__ g1, const float* __restrict__ b1,
                            const float* __restrict__ g2, const float* __restrict__ b2) {
    __shared__ float sh[256];
    int n = blockIdx.x, t = threadIdx.x;
    float v = x[(size_t)n * 256 + t];

    sh[t] = v; __syncthreads();
    for (int o = 128; o; o >>= 1) { if (t < o) sh[t] += sh[t + o]; __syncthreads(); }
    float mu = sh[0] * (1.f / 256.f); __syncthreads();
    float d = v - mu;
    sh[t] = d * d; __syncthreads();
    for (int o = 128; o; o >>= 1) { if (t < o) sh[t] += sh[t + o]; __syncthreads(); }
    float var = sh[0] * (1.f / 256.f); __syncthreads();
    v = d * rsqrtf(var + 1e-5f) * g1[t] + b1[t];

    sh[t] = v; __syncthreads();
    for (int o = 128; o; o >>= 1) { if (t < o) sh[t] += sh[t + o]; __syncthreads(); }
    mu = sh[0] * (1.f / 256.f); __syncthreads();
    d = v - mu;
    sh[t] = d * d; __syncthreads();
    for (int o = 128; o; o >>= 1) { if (t < o) sh[t] += sh[t + o]; __syncthreads(); }
    var = sh[0] * (1.f / 256.f); __syncthreads();
    v = d * rsqrtf(var + 1e-5f) * g2[t] + b2[t];

    x[(size_t)n * 256 + t] = v;
}

// ================= mean pool =================
__global__ void k_zero_out(float* out) { out[threadIdx.x] = 0.f; }
__global__ void k_pool(const float* __restrict__ x, float* __restrict__ out) {
    int t = threadIdx.x;
    int b = blockIdx.x;
    int rows_per = (N_NODES + gridDim.x - 1) / gridDim.x;
    int r0 = b * rows_per;
    int r1 = min(r0 + rows_per, N_NODES);
    float acc = 0.f;
    for (int r = r0; r < r1; r++) acc += x[(size_t)r * 256 + t];
    atomicAdd(&out[t], acc * (1.f / (float)N_NODES));
}

// ================= launch =================
extern "C" void kernel_launch(void* const* d_in, const int* in_sizes, int n_in,
                              void* d_out, int out_size) {
    const float* multi_hot = (const float*)d_in[0];
    const float* bert_feat = (const float*)d_in[1];
    const int*   edge      = (const int*)d_in[2];
    const float* W_struct  = (const float*)d_in[3];
    const float* b_struct  = (const float*)d_in[4];
    const float* W_bert    = (const float*)d_in[5];
    const float* b_bert    = (const float*)d_in[6];
    const float* W_g1      = (const float*)d_in[7];
    const float* att_src1  = (const float*)d_in[8];
    const float* att_dst1  = (const float*)d_in[9];
    const float* b_g1      = (const float*)d_in[10];
    const float* W_g2      = (const float*)d_in[11];
    const float* att_src2  = (const float*)d_in[12];
    const float* att_dst2  = (const float*)d_in[13];
    const float* b_g2      = (const float*)d_in[14];
    const float* W_g3      = (const float*)d_in[15];
    const float* att_src3  = (const float*)d_in[16];
    const float* att_dst3  = (const float*)d_in[17];
    const float* b_g3      = (const float*)d_in[18];
    const float* ln1_g     = (const float*)d_in[19];
    const float* ln1_b     = (const float*)d_in[20];
    const float* ln2_g     = (const float*)d_in[21];
    const float* ln2_b     = (const float*)d_in[22];
    float* out = (float*)d_out;

    const int* e_src = edge;
    const int* e_dst = edge + E_EDGES;

    float* B2;
    __half *bert16, *fused, *x1, *x2, *xl, *Wt;
    cudaGetSymbolAddress((void**)&xl, g_xl);
    cudaGetSymbolAddress((void**)&B2, g_B2);
    cudaGetSymbolAddress((void**)&bert16, g_bert);
    cudaGetSymbolAddress((void**)&fused, g_fused);
    cudaGetSymbolAddress((void**)&x1, g_x1);
    cudaGetSymbolAddress((void**)&x2, g_x2);
    cudaGetSymbolAddress((void**)&Wt, g_Wt);

    const int SMEM = 3 * 2 * 128 * 80;   // 61440
    cudaFuncSetAttribute(k_hgemm, cudaFuncAttributeMaxDynamicSharedMemorySize, SMEM);

    const int MB = (N_NODES + 127) / 128;   // 391

    // launches 1-3: bert convert, W_bert transpose, deg zero
    {
        size_t n4 = (size_t)N_NODES * 768 / 4;
        k_f32_to_f16<<<(unsigned)((n4 + 255) / 256), 256>>>(bert_feat, bert16, n4);
    }
    k_transp<<<dim3(128 / 32, 768 / 32), dim3(32, 8)>>>(W_bert, Wt, 768, 128);
    k_zero_deg<<<(N_NODES + 255) / 256, 256>>>();

    // launch 4: bert GEMM (profiled slot)
    k_hgemm<<<dim3(1, MB), 256, SMEM>>>(bert16, Wt, fused + 128, N_NODES, 768, 256, b_bert);

    // launches 5+: struct proj + CSR build
    k_struct_proj<<<(N_NODES + 7) / 8, 256>>>(multi_hot, W_struct, b_struct, fused);
    k_count_deg<<<(E_EDGES + 255) / 256, 256>>>(e_dst);
    k_scan_deg<<<1, 1024>>>();
    k_scatter<<<(E_EDGES + 255) / 256, 256>>>(e_src, e_dst);

    // --- GAT1: 256 -> (2,128) mean -> 128 ---
    k_transp<<<dim3(256 / 32, 256 / 32), dim3(32, 8)>>>(W_g1, Wt, 256, 256);
    k_hgemm<<<dim3(2, MB), 256, SMEM>>>(fused, Wt, xl, N_NODES, 256, 256, nullptr);
    k_att_prep<2, 128><<<(N_NODES * 2 + 7) / 8, 256>>>(xl, att_src1, att_dst1);
    k_attention<2><<<(N_NODES * 2 + 255) / 256, 256>>>();
    k_agg_mean_2_128<<<N_NODES, 64>>>(xl, b_g1, x1);

    // --- GAT2: 128 -> (4,256) concat -> 1024, relu ---
    k_transp<<<dim3(1024 / 32, 128 / 32), dim3(32, 8)>>>(W_g2, Wt, 128, 1024);
    k_hgemm<<<dim3(8, MB), 256, SMEM>>>(x1, Wt, xl, N_NODES, 128, 1024, nullptr);
    k_att_prep<4, 256><<<(N_NODES * 4 + 7) / 8, 256>>>(xl, att_src2, att_dst2);
    k_attention<4><<<(N_NODES * 4 + 255) / 256, 256>>>();
    k_agg_concat_relu<<<N_NODES, 256>>>(xl, b_g2, x2);

    // --- GAT3: 1024 -> (4,256) mean -> 256 ---
    k_transp<<<dim3(1024 / 32, 1024 / 32), dim3(32, 8)>>>(W_g3, Wt, 1024, 1024);
    k_hgemm<<<dim3(8, MB), 256, SMEM>>>(x2, Wt, xl, N_NODES, 1024, 1024, nullptr);
    k_att_prep<4, 256><<<(N_NODES * 4 + 7) / 8, 256>>>(xl, att_src3, att_dst3);
    k_attention<4><<<(N_NODES * 4 + 255) / 256, 256>>>();
    k_agg_mean_4_256<<<N_NODES, 128>>>(xl, b_g3, B2);

    // --- double LN + mean pool ---
    k_double_ln<<<N_NODES, 256>>>(B2, ln1_g, ln1_b, ln2_g, ln2_b);
    k_zero_out<<<1, 256>>>(out);
    k_pool<<<200, 256>>>(B2, out);
}

// round 10
// speedup vs baseline: 3.5839x; 1.1190x over previous
#include <cuda_runtime.h>
#include <cuda_fp16.h>
#include <math.h>
#include <stdint.h>

#define N_NODES 50000
#define E_EDGES 200000
#define A_DIM   2000
#define LRELU_S 0.2f

// ================= helpers =================
__device__ __forceinline__ uint32_t smem_u32(const void* p) {
    uint32_t a;
    asm("{ .reg .u64 t; cvta.to.shared.u64 t, %1; cvt.u32.u64 %0, t; }" : "=r"(a) : "l"(p));
    return a;
}
#define CP_ASYNC16(dst, src) \
    asm volatile("cp.async.cg.shared.global [%0], [%1], 16;" :: "r"((uint32_t)(dst)), "l"(src) : "memory")
#define CP_COMMIT() asm volatile("cp.async.commit_group;" ::: "memory")
#define CP_WAIT(n)  asm volatile("cp.async.wait_group %0;" :: "n"(n) : "memory")

#define LDSM_X4(r0, r1, r2, r3, a) \
    asm volatile("ldmatrix.sync.aligned.m8n8.x4.shared.b16 {%0,%1,%2,%3}, [%4];" \
        : "=r"(r0), "=r"(r1), "=r"(r2), "=r"(r3) : "r"(a))
#define LDSM_X2(r0, r1, a) \
    asm volatile("ldmatrix.sync.aligned.m8n8.x2.shared.b16 {%0,%1}, [%2];" \
        : "=r"(r0), "=r"(r1) : "r"(a))

__device__ __forceinline__ void mma16816(float& c0, float& c1, float& c2, float& c3,
                                         uint32_t a0, uint32_t a1, uint32_t a2, uint32_t a3,
                                         uint32_t b0, uint32_t b1) {
    asm volatile("mma.sync.aligned.m16n8k16.row.col.f32.f16.f16.f32 "
                 "{%0,%1,%2,%3}, {%4,%5,%6,%7}, {%8,%9}, {%0,%1,%2,%3};"
                 : "+f"(c0), "+f"(c1), "+f"(c2), "+f"(c3)
                 : "r"(a0), "r"(a1), "r"(a2), "r"(a3), "r"(b0), "r"(b1));
}

// ================= scratch (static globals) =================
__device__ __half g_xl[(size_t)N_NODES * 1024];     // GEMM fp16 out
__device__ float  g_B2[(size_t)N_NODES * 256];      // pool partial buffer (first 256*256 used)
__device__ __half g_bert[(size_t)N_NODES * 768];    // fp16 bert
__device__ __half g_fused[(size_t)N_NODES * 256];   // fp16 fused features
__device__ __half g_x1[(size_t)N_NODES * 128];      // fp16 gat1 agg
__device__ __half g_x2[(size_t)N_NODES * 1024];     // fp16 gat2 agg (relu)
__device__ __half g_Wt[1024 * 1024];                // fp16 transposed weights
__device__ float g_asrc[N_NODES * 4];
__device__ float g_adst[N_NODES * 4];
__device__ float g_alpha[(size_t)E_EDGES * 4];
__device__ float g_alpha_self[N_NODES * 4];
__device__ int   g_deg[N_NODES];
__device__ int   g_off[N_NODES + 1];
__device__ int   g_cur[N_NODES];
__device__ int   g_csrc[E_EDGES];

__device__ __forceinline__ float lrelu(float x) { return x >= 0.f ? x : LRELU_S * x; }

// ================= CSR build =================
__global__ void k_zero_deg() {
    int i = blockIdx.x * blockDim.x + threadIdx.x;
    if (i < N_NODES) g_deg[i] = 0;
}
__global__ void k_count_deg(const int* __restrict__ dst) {
    int e = blockIdx.x * blockDim.x + threadIdx.x;
    if (e < E_EDGES) atomicAdd(&g_deg[dst[e]], 1);
}
__global__ void k_scan_deg() {
    __shared__ int part[1024];
    int t = threadIdx.x;
    const int chunk = (N_NODES + 1023) / 1024;
    int s = 0;
    for (int i = 0; i < chunk; i++) {
        int idx = t * chunk + i;
        if (idx < N_NODES) s += g_deg[idx];
    }
    part[t] = s;
    __syncthreads();
    int val = s;
    for (int o = 1; o < 1024; o <<= 1) {
        int add = (t >= o) ? part[t - o] : 0;
        __syncthreads();
        val += add;
        part[t] = val;
        __syncthreads();
    }
    int base = val - s;
    for (int i = 0; i < chunk; i++) {
        int idx = t * chunk + i;
        if (idx < N_NODES) {
            g_off[idx] = base;
            g_cur[idx] = base;
            base += g_deg[idx];
        }
    }
    if (t == 0) g_off[N_NODES] = E_EDGES;
}
__global__ void k_scatter(const int* __restrict__ src, const int* __restrict__ dst) {
    int e = blockIdx.x * blockDim.x + threadIdx.x;
    if (e < E_EDGES) {
        int p = atomicAdd(&g_cur[dst[e]], 1);
        g_csrc[p] = src[e];
    }
}

// ================= converts =================
__global__ void k_f32_to_f16(const float* __restrict__ in, __half* __restrict__ out, size_t n4) {
    size_t i = (size_t)blockIdx.x * blockDim.x + threadIdx.x;
    if (i < n4) {
        float4 v = reinterpret_cast<const float4*>(in)[i];
        __half2 h0 = __floats2half2_rn(v.x, v.y);
        __half2 h1 = __floats2half2_rn(v.z, v.w);
        uint2 u;
        u.x = *reinterpret_cast<uint32_t*>(&h0);
        u.y = *reinterpret_cast<uint32_t*>(&h1);
        reinterpret_cast<uint2*>(out)[i] = u;
    }
}
// Tiled transpose: Wt[n*K + k] = (half)W[k*N + n]. K, N multiples of 32.
__global__ void k_transp(const float* __restrict__ W, __half* __restrict__ Wt, int K, int N) {
    __shared__ float tile[32][33];
    int k0 = blockIdx.y * 32, n0 = blockIdx.x * 32;
    int tx = threadIdx.x, ty = threadIdx.y;   // block 32x8
#pragma unroll
    for (int i = 0; i < 32; i += 8)
        tile[ty + i][tx] = W[(size_t)(k0 + ty + i) * N + n0 + tx];
    __syncthreads();
#pragma unroll
    for (int i = 0; i < 32; i += 8)
        Wt[(size_t)(n0 + ty + i) * K + k0 + tx] = __float2half(tile[tx][ty + i]);
}

// ================= struct projection (sparse {0,1} matmul) -> fp16 =================
__global__ void k_struct_proj(const float* __restrict__ mh, const float* __restrict__ W,
                              const float* __restrict__ b, __half* __restrict__ outB) {
    int warp = (blockIdx.x * blockDim.x + threadIdx.x) >> 5;
    int lane = threadIdx.x & 31;
    if (warp >= N_NODES) return;
    const float* row = mh + (size_t)warp * A_DIM;
    float a0 = 0.f, a1 = 0.f, a2 = 0.f, a3 = 0.f;
    for (int k0 = 0; k0 < A_DIM; k0 += 32) {
        int k = k0 + lane;
        float v = (k < A_DIM) ? row[k] : 0.f;
        unsigned m = __ballot_sync(0xffffffffu, v != 0.f);
        while (m) {
            int j = __ffs(m) - 1;
            m &= m - 1;
            float vj = __shfl_sync(0xffffffffu, v, j);
            const float* wr = W + (size_t)(k0 + j) * 128;
            a0 += wr[lane] * vj;
            a1 += wr[lane + 32] * vj;
            a2 += wr[lane + 64] * vj;
            a3 += wr[lane + 96] * vj;
        }
    }
    __half* o = outB + (size_t)warp * 256;
    o[lane]      = __float2half(a0 + b[lane]);
    o[lane + 32] = __float2half(a1 + b[lane + 32]);
    o[lane + 64] = __float2half(a2 + b[lane + 64]);
    o[lane + 96] = __float2half(a3 + b[lane + 96]);
}

// ================= fp16 HMMA GEMM (ldmatrix) =================
// C[M, N] = A[M, K] @ Wt[N, K]^T  (fp16 in, fp32 acc, fp16 out)
// BM=128, BN=128, BK=32, 256 threads, 8 warps (2 m x 4 n), warp tile 64x32.
// S=3 stages, 2 CTAs/SM. smem row stride 80B (ldmatrix-conflict-free).
__global__ void __launch_bounds__(256, 2)
k_hgemm(const __half* __restrict__ A, const __half* __restrict__ Bt,
        __half* __restrict__ C, int M, int K, int ldc, const float* __restrict__ bias) {
    constexpr int S = 3;
    constexpr int TILE_BYTES = 128 * 80;
    constexpr int STAGE = 2 * TILE_BYTES;

    extern __shared__ char smem[];
    uint32_t sb = smem_u32(smem);

    int tid = threadIdx.x;
    int wid = tid >> 5;
    int lane = tid & 31;
    int wm = wid & 1;
    int wn = wid >> 1;
    int bm = blockIdx.y * 128;
    int bn = blockIdx.x * 128;
    int KI = K / 32;

    int qrow = lane >> 2;
    int qcol = (lane & 3) * 2;

    // ldmatrix per-lane address offsets (within a tile at row base 0, k base 0)
    // A (x4): group 0: rows 0-7 k 0-7; 1: rows 8-15 k 0-7; 2: rows 0-7 k 8-15; 3: rows 8-15 k 8-15
    uint32_t a_off = (uint32_t)(((lane & 7) + ((lane >> 3) & 1) * 8) * 80 + (lane >> 4) * 16);
    // B (x2): group 0: rows(n) 0-7 k 0-7; 1: rows 0-7 k 8-15 (lanes 16-31 ignored)
    uint32_t b_off = (uint32_t)((lane & 7) * 80 + ((lane >> 3) & 1) * 16);

    float acc[4][4][4];
#pragma unroll
    for (int i = 0; i < 4; i++)
#pragma unroll
        for (int j = 0; j < 4; j++)
#pragma unroll
            for (int r = 0; r < 4; r++) acc[i][j][r] = 0.f;

    auto load_stage = [&](int kt, int s) {
        int k0 = kt * 32;
#pragma unroll
        for (int j = 0; j < 2; j++) {
            int ci = tid + j * 256;
            int row = ci >> 2, cp = ci & 3;
            uint32_t dst = sb + s * STAGE + row * 80 + cp * 16;
            if (bm + row < M)
                CP_ASYNC16(dst, A + (size_t)(bm + row) * K + k0 + cp * 8);
        }
#pragma unroll
        for (int j = 0; j < 2; j++) {
            int ci = tid + j * 256;
            int row = ci >> 2, cp = ci & 3;
            uint32_t dst = sb + s * STAGE + TILE_BYTES + row * 80 + cp * 16;
            CP_ASYNC16(dst, Bt + (size_t)(bn + row) * K + k0 + cp * 8);
        }
    };

    load_stage(0, 0); CP_COMMIT();
    if (KI > 1) load_stage(1, 1);
    CP_COMMIT();

    for (int kt = 0; kt < KI; kt++) {
        int s = kt % S;
        CP_WAIT(1);
        __syncthreads();
        uint32_t a_base = sb + s * STAGE + (uint32_t)(wm * 64 * 80) + a_off;
        uint32_t b_base = sb + s * STAGE + TILE_BYTES + (uint32_t)(wn * 32 * 80) + b_off;
#pragma unroll
        for (int kk = 0; kk < 32; kk += 16) {
            uint32_t af[4][4], bf[4][2];
#pragma unroll
            for (int mt = 0; mt < 4; mt++)
                LDSM_X4(af[mt][0], af[mt][1], af[mt][2], af[mt][3],
                        a_base + (uint32_t)(mt * 16 * 80 + kk * 2));
#pragma unroll
            for (int nt = 0; nt < 4; nt++)
                LDSM_X2(bf[nt][0], bf[nt][1],
                        b_base + (uint32_t)(nt * 8 * 80 + kk * 2));
#pragma unroll
            for (int mt = 0; mt < 4; mt++)
#pragma unroll
                for (int nt = 0; nt < 4; nt++)
                    mma16816(acc[mt][nt][0], acc[mt][nt][1], acc[mt][nt][2], acc[mt][nt][3],
                             af[mt][0], af[mt][1], af[mt][2], af[mt][3],
                             bf[nt][0], bf[nt][1]);
        }
        int kn = kt + 2;
        if (kn < KI) load_stage(kn, kn % S);
        CP_COMMIT();
    }

    // ---- epilogue (fp16 out) ----
#pragma unroll
    for (int mt = 0; mt < 4; mt++) {
        int r0 = bm + wm * 64 + mt * 16 + qrow;
#pragma unroll
        for (int nt = 0; nt < 4; nt++) {
            int c = bn + wn * 32 + nt * 8 + qcol;
            float v0 = acc[mt][nt][0], v1 = acc[mt][nt][1];
            float v2 = acc[mt][nt][2], v3 = acc[mt][nt][3];
            if (bias) {
                float b0 = bias[c], b1 = bias[c + 1];
                v0 += b0; v1 += b1; v2 += b0; v3 += b1;
            }
            if (r0 < M)
                *reinterpret_cast<__half2*>(C + (size_t)r0 * ldc + c) = __floats2half2_rn(v0, v1);
            if (r0 + 8 < M)
                *reinterpret_cast<__half2*>(C + (size_t)(r0 + 8) * ldc + c) = __floats2half2_rn(v2, v3);
        }
    }
}

// ================= attention scores (fp16 xl) =================
template <int H, int C>
__global__ void k_att_prep(const __half* __restrict__ xl, const float* __restrict__ att_src,
                           const float* __restrict__ att_dst) {
    int warp = (blockIdx.x * blockDim.x + threadIdx.x) >> 5;
    int lane = threadIdx.x & 31;
    if (warp >= N_NODES * H) return;
    int n = warp / H, h = warp % H;
    const __half* row = xl + (size_t)n * (H * C) + h * C;
    float s = 0.f, d = 0.f;
#pragma unroll
    for (int i = 0; i < C / 64; i++) {
        int c = i * 64 + lane * 2;
        float2 v = __half22float2(*reinterpret_cast<const __half2*>(row + c));
        s += v.x * att_src[h * C + c] + v.y * att_src[h * C + c + 1];
        d += v.x * att_dst[h * C + c] + v.y * att_dst[h * C + c + 1];
    }
#pragma unroll
    for (int o = 16; o; o >>= 1) {
        s += __shfl_down_sync(0xffffffffu, s, o);
        d += __shfl_down_sync(0xffffffffu, d, o);
    }
    if (lane == 0) {
        g_asrc[n * H + h] = s;
        g_adst[n * H + h] = d;
    }
}

template <int H>
__global__ void k_attention() {
    int idx = blockIdx.x * blockDim.x + threadIdx.x;
    if (idx >= N_NODES * H) return;
    int n = idx / H, h = idx % H;
    float ad = g_adst[n * H + h];
    int s0 = g_off[n], s1 = g_off[n + 1];
    float eself = lrelu(g_asrc[n * H + h] + ad);
    float mx = eself;
    for (int s = s0; s < s1; s++) {
        float e = lrelu(g_asrc[g_csrc[s] * H + h] + ad);
        mx = fmaxf(mx, e);
    }
    float denom = __expf(eself - mx);
    for (int s = s0; s < s1; s++) {
        float e = lrelu(g_asrc[g_csrc[s] * H + h] + ad);
        denom += __expf(e - mx);
    }
    float inv = 1.f / (denom + 1e-16f);
    g_alpha_self[n * H + h] = __expf(eself - mx) * inv;
    for (int s = s0; s < s1; s++) {
        float e = lrelu(g_asrc[g_csrc[s] * H + h] + ad);
        g_alpha[(size_t)s * H + h] = __expf(e - mx) * inv;
    }
}

// ================= aggregation (fp16 xl in) =================
__global__ void k_agg_mean_2_128(const __half* __restrict__ xl,
                                 const float* __restrict__ bias, __half* __restrict__ out) {
    int n = blockIdx.x;
    int t = threadIdx.x;
    int s0 = g_off[n], s1 = g_off[n + 1];
    float a0 = 0.f, a1 = 0.f;
#pragma unroll
    for (int h = 0; h < 2; h++) {
        float al = g_alpha_self[n * 2 + h];
        float2 v = __half22float2(
            *reinterpret_cast<const __half2*>(xl + (size_t)n * 256 + h * 128 + 2 * t));
        a0 += al * v.x; a1 += al * v.y;
    }
    for (int s = s0; s < s1; s++) {
        int src = g_csrc[s];
#pragma unroll
        for (int h = 0; h < 2; h++) {
            float al = g_alpha[(size_t)s * 2 + h];
            float2 v = __half22float2(
                *reinterpret_cast<const __half2*>(xl + (size_t)src * 256 + h * 128 + 2 * t));
            a0 += al * v.x; a1 += al * v.y;
        }
    }
    *reinterpret_cast<__half2*>(out + (size_t)n * 128 + 2 * t) =
        __floats2half2_rn(a0 * 0.5f + bias[2 * t], a1 * 0.5f + bias[2 * t + 1]);
}

__global__ void k_agg_concat_relu(const __half* __restrict__ xl,
                                  const float* __restrict__ bias, __half* __restrict__ out) {
    int n = blockIdx.x;
    int t = threadIdx.x;
    int j = t >> 6;
    int c0 = 4 * t;
    int s0 = g_off[n], s1 = g_off[n + 1];
    float a0, a1, a2, a3;
    {
        float al = g_alpha_self[n * 4 + j];
        uint2 u = *reinterpret_cast<const uint2*>(xl + (size_t)n * 1024 + c0);
        float2 p = __half22float2(*reinterpret_cast<__half2*>(&u.x));
        float2 q = __half22float2(*reinterpret_cast<__half2*>(&u.y));
        a0 = al * p.x; a1 = al * p.y; a2 = al * q.x; a3 = al * q.y;
    }
    for (int s = s0; s < s1; s++) {
        int src = g_csrc[s];
        float al = g_alpha[(size_t)s * 4 + j];
        uint2 u = *reinterpret_cast<const uint2*>(xl + (size_t)src * 1024 + c0);
        float2 p = __half22float2(*reinterpret_cast<__half2*>(&u.x));
        float2 q = __half22float2(*reinterpret_cast<__half2*>(&u.y));
        a0 += al * p.x; a1 += al * p.y; a2 += al * q.x; a3 += al * q.y;
    }
    __half2 h0 = __floats2half2_rn(fmaxf(a0 + bias[c0], 0.f),     fmaxf(a1 + bias[c0 + 1], 0.f));
    __half2 h1 = __floats2half2_rn(fmaxf(a2 + bias[c0 + 2], 0.f), fmaxf(a3 + bias[c0 + 3], 0.f));
    uint2 u;
    u.x = *reinterpret_cast<uint32_t*>(&h0);
    u.y = *reinterpret_cast<uint32_t*>(&h1);
    *reinterpret_cast<uint2*>(out + (size_t)n * 1024 + c0) = u;
}

// gat3 agg + double LayerNorm + partial mean-pool, fused.
// 128 threads; thread t -> cols 2t, 2t+1. Partial pool into partial[(n&255)*256 + c].
__global__ void k_agg3_ln_pool(const __half* __restrict__ xl, const float* __restrict__ bias,
                               const float* __restrict__ g1, const float* __restrict__ b1,
                               const float* __restrict__ g2, const float* __restrict__ b2,
                               float* __restrict__ partial) {
    __shared__ float sh[128];
    int n = blockIdx.x;
    int t = threadIdx.x;
    int s0 = g_off[n], s1 = g_off[n + 1];
    float a0 = 0.f, a1 = 0.f;
#pragma unroll
    for (int h = 0; h < 4; h++) {
        float al = g_alpha_self[n * 4 + h];
        float2 v = __half22float2(
            *reinterpret_cast<const __half2*>(xl + (size_t)n * 1024 + h * 256 + 2 * t));
        a0 += al * v.x; a1 += al * v.y;
    }
    for (int s = s0; s < s1; s++) {
        int src = g_csrc[s];
        const __half* xr = xl + (size_t)src * 1024 + 2 * t;
#pragma unroll
        for (int h = 0; h < 4; h++) {
            float al = g_alpha[(size_t)s * 4 + h];
            float2 v = __half22float2(*reinterpret_cast<const __half2*>(xr + h * 256));
            a0 += al * v.x; a1 += al * v.y;
        }
    }
    float v0 = a0 * 0.25f + bias[2 * t];
    float v1 = a1 * 0.25f + bias[2 * t + 1];

    // LN1
    sh[t] = v0 + v1; __syncthreads();
    for (int o = 64; o; o >>= 1) { if (t < o) sh[t] += sh[t + o]; __syncthreads(); }
    float mu = sh[0] * (1.f / 256.f); __syncthreads();
    float d0 = v0 - mu, d1 = v1 - mu;
    sh[t] = d0 * d0 + d1 * d1; __syncthreads();
    for (int o = 64; o; o >>= 1) { if (t < o) sh[t] += sh[t + o]; __syncthreads(); }
    float inv = rsqrtf(sh[0] * (1.f / 256.f) + 1e-5f); __syncthreads();
    v0 = d0 * inv * g1[2 * t] + b1[2 * t];
    v1 = d1 * inv * g1[2 * t + 1] + b1[2 * t + 1];

    // LN2
    sh[t] = v0 + v1; __syncthreads();
    for (int o = 64; o; o >>= 1) { if (t < o) sh[t] += sh[t + o]; __syncthreads(); }
    mu = sh[0] * (1.f / 256.f); __syncthreads();
    d0 = v0 - mu; d1 = v1 - mu;
    sh[t] = d0 * d0 + d1 * d1; __syncthreads();
    for (int o = 64; o; o >>= 1) { if (t < o) sh[t] += sh[t + o]; __syncthreads(); }
    inv = rsqrtf(sh[0] * (1.f / 256.f) + 1e-5f);
    v0 = d0 * inv * g2[2 * t] + b2[2 * t];
    v1 = d1 * inv * g2[2 * t + 1] + b2[2 * t + 1];

    float* p = partial + (size_t)(n & 255) * 256 + 2 * t;
    atomicAdd(p, v0);
    atomicAdd(p + 1, v1);
}

__global__ void k_zero_partial(float* __restrict__ partial) {
    int i = blockIdx.x * blockDim.x + threadIdx.x;
    if (i < 256 * 256) partial[i] = 0.f;
}
__global__ void k_pool_final(const float* __restrict__ partial, float* __restrict__ out) {
    int t = threadIdx.x;   // 256
    float s = 0.f;
    for (int i = 0; i < 256; i++) s += partial[(size_t)i * 256 + t];
    out[t] = s * (1.f / (float)N_NODES);
}

// ================= launch =================
extern "C" void kernel_launch(void* const* d_in, const int* in_sizes, int n_in,
                              void* d_out, int out_size) {
    const float* multi_hot = (const float*)d_in[0];
    const float* bert_feat = (const float*)d_in[1];
    const int*   edge      = (const int*)d_in[2];
    const float* W_struct  = (const float*)d_in[3];
    const float* b_struct  = (const float*)d_in[4];
    const float* W_bert    = (const float*)d_in[5];
    const float* b_bert    = (const float*)d_in[6];
    const float* W_g1      = (const float*)d_in[7];
    const float* att_src1  = (const float*)d_in[8];
    const float* att_dst1  = (const float*)d_in[9];
    const float* b_g1      = (const float*)d_in[10];
    const float* W_g2      = (const float*)d_in[11];
    const float* att_src2  = (const float*)d_in[12];
    const float* att_dst2  = (const float*)d_in[13];
    const float* b_g2      = (const float*)d_in[14];
    const float* W_g3      = (const float*)d_in[15];
    const float* att_src3  = (const float*)d_in[16];
    const float* att_dst3  = (const float*)d_in[17];
    const float* b_g3      = (const float*)d_in[18];
    const float* ln1_g     = (const float*)d_in[19];
    const float* ln1_b     = (const float*)d_in[20];
    const float* ln2_g     = (const float*)d_in[21];
    const float* ln2_b     = (const float*)d_in[22];
    float* out = (float*)d_out;

    const int* e_src = edge;
    const int* e_dst = edge + E_EDGES;

    float* B2;
    __half *bert16, *fused, *x1, *x2, *xl, *Wt;
    cudaGetSymbolAddress((void**)&xl, g_xl);
    cudaGetSymbolAddress((void**)&B2, g_B2);
    cudaGetSymbolAddress((void**)&bert16, g_bert);
    cudaGetSymbolAddress((void**)&fused, g_fused);
    cudaGetSymbolAddress((void**)&x1, g_x1);
    cudaGetSymbolAddress((void**)&x2, g_x2);
    cudaGetSymbolAddress((void**)&Wt, g_Wt);

    const int SMEM = 3 * 2 * 128 * 80;   // 61440
    cudaFuncSetAttribute(k_hgemm, cudaFuncAttributeMaxDynamicSharedMemorySize, SMEM);

    const int MB = (N_NODES + 127) / 128;   // 391

    // launches 1-3: bert convert, W_bert transpose, deg zero
    {
        size_t n4 = (size_t)N_NODES * 768 / 4;
        k_f32_to_f16<<<(unsigned)((n4 + 255) / 256), 256>>>(bert_feat, bert16, n4);
    }
    k_transp<<<dim3(128 / 32, 768 / 32), dim3(32, 8)>>>(W_bert, Wt, 768, 128);
    k_zero_deg<<<(N_NODES + 255) / 256, 256>>>();

    // launch 4: bert GEMM (profiled slot)
    k_hgemm<<<dim3(1, MB), 256, SMEM>>>(bert16, Wt, fused + 128, N_NODES, 768, 256, b_bert);

    // launches 5+: struct proj + CSR build
    k_struct_proj<<<(N_NODES + 7) / 8, 256>>>(multi_hot, W_struct, b_struct, fused);
    k_count_deg<<<(E_EDGES + 255) / 256, 256>>>(e_dst);
    k_scan_deg<<<1, 1024>>>();
    k_scatter<<<(E_EDGES + 255) / 256, 256>>>(e_src, e_dst);

    // --- GAT1: 256 -> (2,128) mean -> 128 ---
    k_transp<<<dim3(256 / 32, 256 / 32), dim3(32, 8)>>>(W_g1, Wt, 256, 256);
    k_hgemm<<<dim3(2, MB), 256, SMEM>>>(fused, Wt, xl, N_NODES, 256, 256, nullptr);
    k_att_prep<2, 128><<<(N_NODES * 2 + 7) / 8, 256>>>(xl, att_src1, att_dst1);
    k_attention<2><<<(N_NODES * 2 + 255) / 256, 256>>>();
    k_agg_mean_2_128<<<N_NODES, 64>>>(xl, b_g1, x1);

    // --- GAT2: 128 -> (4,256) concat -> 1024, relu ---
    k_transp<<<dim3(1024 / 32, 128 / 32), dim3(32, 8)>>>(W_g2, Wt, 128, 1024);
    k_hgemm<<<dim3(8, MB), 256, SMEM>>>(x1, Wt, xl, N_NODES, 128, 1024, nullptr);
    k_att_prep<4, 256><<<(N_NODES * 4 + 7) / 8, 256>>>(xl, att_src2, att_dst2);
    k_attention<4><<<(N_NODES * 4 + 255) / 256, 256>>>();
    k_agg_concat_relu<<<N_NODES, 256>>>(xl, b_g2, x2);

    // --- GAT3: 1024 -> (4,256) mean -> 256, fused LN+pool ---
    k_transp<<<dim3(1024 / 32, 1024 / 32), dim3(32, 8)>>>(W_g3, Wt, 1024, 1024);
    k_hgemm<<<dim3(8, MB), 256, SMEM>>>(x2, Wt, xl, N_NODES, 1024, 1024, nullptr);
    k_att_prep<4, 256><<<(N_NODES * 4 + 7) / 8, 256>>>(xl, att_src3, att_dst3);
    k_attention<4><<<(N_NODES * 4 + 255) / 256, 256>>>();
    k_zero_partial<<<(256 * 256 + 255) / 256, 256>>>(B2);
    k_agg3_ln_pool<<<N_NODES, 128>>>(xl, b_g3, ln1_g, ln1_b, ln2_g, ln2_b, B2);
    k_pool_final<<<1, 256>>>(B2, out);
}